// round 14
// baseline (speedup 1.0000x reference)
#include <cuda_runtime.h>
#include <math.h>

#define NN 50000
#define FD 512
#define NH 4

constexpr int MAX_S  = 8192;
constexpr int MAX_U  = 262144;
constexpr int MAXDEG = 128;
constexpr int MAXIDS = 32;
constexpr int NMSK   = 1600;   // ceil(50000/32)

// ---------------- static device scratch ----------------
__device__ float4 g_el4[NN];
__device__ float4 g_er4[NN];
__device__ float  g_z[(size_t)MAX_S * NH * FD];
__device__ float  g_h1p[(size_t)MAX_S * FD];
__device__ float4 g_el1_4[MAX_S];
__device__ float4 g_er1_4[MAX_S];
__device__ float  g_z2[(size_t)MAXIDS * NH * FD];
__device__ float4 g_wl0_4[FD], g_wr0_4[FD], g_wl1_4[FD], g_wr1_4[FD];
__device__ unsigned g_mskS[NMSK], g_mskU[NMSK];
__device__ int g_S[MAX_S], g_posS[NN], g_degS[MAX_S];
__device__ int g_bkt[(size_t)MAX_S * MAXDEG];
__device__ int g_U[MAX_U];
__device__ int g_nS, g_nU;

// ---------------- helpers ----------------
__device__ __forceinline__ unsigned long long dup2(float a) {
    unsigned long long r;
    unsigned int ai = __float_as_uint(a);
    asm("mov.b64 %0, {%1, %1};" : "=l"(r) : "r"(ai));
    return r;
}
__device__ __forceinline__ void fma2(unsigned long long& d, unsigned long long a, unsigned long long b) {
    asm("fma.rn.f32x2 %0, %1, %2, %0;" : "+l"(d) : "l"(a), "l"(b));
}
__device__ __forceinline__ float2 unpack2(unsigned long long v) {
    float2 r;
    r.x = __uint_as_float((unsigned int)(v & 0xffffffffull));
    r.y = __uint_as_float((unsigned int)(v >> 32));
    return r;
}
__device__ __forceinline__ float wredsum(float x) {
    #pragma unroll
    for (int o = 16; o > 0; o >>= 1) x += __shfl_xor_sync(0xffffffffu, x, o);
    return x;
}
__device__ __forceinline__ float wredmax(float x) {
    #pragma unroll
    for (int o = 16; o > 0; o >>= 1) x = fmaxf(x, __shfl_xor_sync(0xffffffffu, x, o));
    return x;
}
__device__ __forceinline__ float eluf(float x) { return (x > 0.f) ? x : expm1f(x); }

// ---------------- setup: zero scratch + projected attention vectors ----------------
__global__ __launch_bounds__(256) void k_setup(const float* __restrict__ W0,
                                               const float* __restrict__ al0, const float* __restrict__ ar0,
                                               const float* __restrict__ W1,
                                               const float* __restrict__ al1, const float* __restrict__ ar1) {
    int gi = blockIdx.x * 256 + threadIdx.x;
    if (gi < MAX_S) {
        g_degS[gi] = 0;
        g_el1_4[gi] = make_float4(0, 0, 0, 0);
        g_er1_4[gi] = make_float4(0, 0, 0, 0);
    }
    if (gi < NMSK) { g_mskS[gi] = 0; g_mskU[gi] = 0; }
    if (gi == 0) { g_nS = 0; g_nU = 0; }

    int lane = threadIdx.x & 31;
    int w = gi >> 5;
    if (w >= FD) return;
    const float4* w0r = reinterpret_cast<const float4*>(W0 + (size_t)w * FD);
    const float4* w1r = reinterpret_cast<const float4*>(W1 + (size_t)w * FD);
    const float4* l0 = reinterpret_cast<const float4*>(al0);
    const float4* r0 = reinterpret_cast<const float4*>(ar0);
    const float4* l1 = reinterpret_cast<const float4*>(al1);
    const float4* r1 = reinterpret_cast<const float4*>(ar1);
    float sl0[NH], sr0[NH], sl1[NH], sr1[NH];
    #pragma unroll
    for (int h = 0; h < NH; h++) {
        float4 a0 = w0r[h * 32 + lane];
        float4 b0l = l0[h * 32 + lane];
        float4 b0r = r0[h * 32 + lane];
        sl0[h] = wredsum(a0.x * b0l.x + a0.y * b0l.y + a0.z * b0l.z + a0.w * b0l.w);
        sr0[h] = wredsum(a0.x * b0r.x + a0.y * b0r.y + a0.z * b0r.z + a0.w * b0r.w);
        float4 a1 = w1r[h * 32 + lane];
        float4 b1l = l1[h * 32 + lane];
        float4 b1r = r1[h * 32 + lane];
        sl1[h] = wredsum(a1.x * b1l.x + a1.y * b1l.y + a1.z * b1l.z + a1.w * b1l.w);
        sr1[h] = wredsum(a1.x * b1r.x + a1.y * b1r.y + a1.z * b1r.z + a1.w * b1r.w);
    }
    if (lane == 0) {
        g_wl0_4[w] = make_float4(sl0[0], sl0[1], sl0[2], sl0[3]);
        g_wr0_4[w] = make_float4(sr0[0], sr0[1], sr0[2], sr0[3]);
        g_wl1_4[w] = make_float4(sl1[0], sl1[1], sl1[2], sl1[3]);
        g_wr1_4[w] = make_float4(sr1[0], sr1[1], sr1[2], sr1[3]);
    }
}

// ---------------- scan e2: edges into ids -> build S (smem id-bitmask) ----------------
__global__ __launch_bounds__(256) void k_scan_e2(const int* __restrict__ src, const int* __restrict__ dst,
                                                 const int* __restrict__ ids, int nIds, int E) {
    __shared__ unsigned smsk[NMSK];
    for (int i = threadIdx.x; i < NMSK; i += 256) smsk[i] = 0;
    __syncthreads();
    if (threadIdx.x < nIds) {
        int v = ids[threadIdx.x];
        atomicOr(&smsk[v >> 5], 1u << (v & 31));
    }
    __syncthreads();
    int i = blockIdx.x * blockDim.x + threadIdx.x;
    int stride = gridDim.x * blockDim.x;
    int E4 = E >> 2;
    const int4* d4 = reinterpret_cast<const int4*>(dst);
    auto proc = [&](int dd, int e) {
        if ((smsk[dd >> 5] >> (dd & 31)) & 1u) {
            int s = src[e];
            unsigned m = 1u << (s & 31);
            unsigned old = atomicOr(&g_mskS[s >> 5], m);
            if (!(old & m)) {
                int p = atomicAdd(&g_nS, 1);
                if (p < MAX_S) { g_S[p] = s; g_posS[s] = p; }
            }
        }
    };
    for (int q = i; q < E4; q += stride) {
        int4 d = d4[q];
        int e = q * 4;
        proc(d.x, e); proc(d.y, e + 1); proc(d.z, e + 2); proc(d.w, e + 3);
    }
    for (int e = E4 * 4 + i; e < E; e += stride) proc(dst[e], e);
}

// ---------------- scan e1: bucket edges into S (smem S-bitmask); build U ----------------
__global__ __launch_bounds__(256) void k_scan_e1(const int* __restrict__ src, const int* __restrict__ dst, int E) {
    __shared__ unsigned smsk[NMSK];
    for (int i = threadIdx.x; i < NMSK; i += 256) smsk[i] = g_mskS[i];
    __syncthreads();
    int i = blockIdx.x * blockDim.x + threadIdx.x;
    int stride = gridDim.x * blockDim.x;
    int E4 = E >> 2;
    const int4* d4 = reinterpret_cast<const int4*>(dst);
    auto proc = [&](int dd, int e) {
        if ((smsk[dd >> 5] >> (dd & 31)) & 1u) {
            int p = g_posS[dd];
            int s = src[e];
            int slot = atomicAdd(&g_degS[p], 1);
            if (slot < MAXDEG) g_bkt[(size_t)p * MAXDEG + slot] = s;
            unsigned m = 1u << (s & 31);
            if (!((g_mskU[s >> 5] >> (s & 31)) & 1u)) {
                unsigned old = atomicOr(&g_mskU[s >> 5], m);
                if (!(old & m)) {
                    int u = atomicAdd(&g_nU, 1);
                    if (u < MAX_U) g_U[u] = s;
                }
            }
        }
    };
    for (int q = i; q < E4; q += stride) {
        int4 d = d4[q];
        int e = q * 4;
        proc(d.x, e); proc(d.y, e + 1); proc(d.z, e + 2); proc(d.w, e + 3);
    }
    for (int e = E4 * 4 + i; e < E; e += stride) proc(dst[e], e);
}

// ---------------- el over U (smem table, low-reg); er over S only ----------------
__global__ __launch_bounds__(256, 4) void k_eler0(const float* __restrict__ X) {
    __shared__ float4 swl[FD];   // 8KB
    for (int k = threadIdx.x; k < FD; k += 256) swl[k] = g_wl0_4[k];
    __syncthreads();
    int lane = threadIdx.x & 31;
    int w = (blockIdx.x * blockDim.x + threadIdx.x) >> 5;
    int nw = (gridDim.x * blockDim.x) >> 5;
    int n = min(g_nU, MAX_U);
    for (int g = w; g < n; g += nw) {
        int v = g_U[g];
        const float4* xr = reinterpret_cast<const float4*>(X + (size_t)v * FD);
        float aL0 = 0, aL1 = 0, aL2 = 0, aL3 = 0;
        #pragma unroll
        for (int i = 0; i < 4; i++) {
            float4 x4 = xr[lane * 4 + i];
            float4 l0 = swl[lane * 16 + i * 4 + 0];
            float4 l1 = swl[lane * 16 + i * 4 + 1];
            float4 l2 = swl[lane * 16 + i * 4 + 2];
            float4 l3 = swl[lane * 16 + i * 4 + 3];
            aL0 = fmaf(x4.x, l0.x, aL0); aL1 = fmaf(x4.x, l0.y, aL1);
            aL2 = fmaf(x4.x, l0.z, aL2); aL3 = fmaf(x4.x, l0.w, aL3);
            aL0 = fmaf(x4.y, l1.x, aL0); aL1 = fmaf(x4.y, l1.y, aL1);
            aL2 = fmaf(x4.y, l1.z, aL2); aL3 = fmaf(x4.y, l1.w, aL3);
            aL0 = fmaf(x4.z, l2.x, aL0); aL1 = fmaf(x4.z, l2.y, aL1);
            aL2 = fmaf(x4.z, l2.z, aL2); aL3 = fmaf(x4.z, l2.w, aL3);
            aL0 = fmaf(x4.w, l3.x, aL0); aL1 = fmaf(x4.w, l3.y, aL1);
            aL2 = fmaf(x4.w, l3.z, aL2); aL3 = fmaf(x4.w, l3.w, aL3);
        }
        aL0 = wredsum(aL0); aL1 = wredsum(aL1); aL2 = wredsum(aL2); aL3 = wredsum(aL3);
        if (lane == 0) g_el4[v] = make_float4(aL0, aL1, aL2, aL3);
    }
    // er pass: only S nodes need er (they are the dsts)
    int nS = min(g_nS, MAX_S);
    for (int g = w; g < nS; g += nw) {
        int v = g_S[g];
        const float4* xr = reinterpret_cast<const float4*>(X + (size_t)v * FD);
        float aR0 = 0, aR1 = 0, aR2 = 0, aR3 = 0;
        #pragma unroll
        for (int i = 0; i < 4; i++) {
            float4 x4 = xr[lane * 4 + i];
            float4 r0 = g_wr0_4[lane * 16 + i * 4 + 0];
            float4 r1 = g_wr0_4[lane * 16 + i * 4 + 1];
            float4 r2 = g_wr0_4[lane * 16 + i * 4 + 2];
            float4 r3 = g_wr0_4[lane * 16 + i * 4 + 3];
            aR0 = fmaf(x4.x, r0.x, aR0); aR1 = fmaf(x4.x, r0.y, aR1);
            aR2 = fmaf(x4.x, r0.z, aR2); aR3 = fmaf(x4.x, r0.w, aR3);
            aR0 = fmaf(x4.y, r1.x, aR0); aR1 = fmaf(x4.y, r1.y, aR1);
            aR2 = fmaf(x4.y, r1.z, aR2); aR3 = fmaf(x4.y, r1.w, aR3);
            aR0 = fmaf(x4.z, r2.x, aR0); aR1 = fmaf(x4.z, r2.y, aR1);
            aR2 = fmaf(x4.z, r2.z, aR2); aR3 = fmaf(x4.z, r2.w, aR3);
            aR0 = fmaf(x4.w, r3.x, aR0); aR1 = fmaf(x4.w, r3.y, aR1);
            aR2 = fmaf(x4.w, r3.z, aR2); aR3 = fmaf(x4.w, r3.w, aR3);
        }
        aR0 = wredsum(aR0); aR1 = wredsum(aR1); aR2 = wredsum(aR2); aR3 = wredsum(aR3);
        if (lane == 0) g_er4[v] = make_float4(aR0, aR1, aR2, aR3);
    }
}

// ---------------- layer-1 per-head aggregation; block = 2 dsts, 4 warps/dst ----------------
__global__ __launch_bounds__(256, 4) void k_agg1(const float* __restrict__ X) {
    __shared__ int   ssrc[2][MAXDEG];
    __shared__ float ssc[2][MAXDEG][NH];
    __shared__ float sinv[2][NH];
    int w = threadIdx.x >> 5, lane = threadIdx.x & 31;
    int nS = min(g_nS, MAX_S);
    int nGrp = (nS + 1) >> 1;
    for (int grp = blockIdx.x; grp < nGrp; grp += gridDim.x) {
        // Phase A: warps 0..1 score dst grp*2+w
        if (w < 2) {
            int p = grp * 2 + w;
            if (p < nS) {
                int v = g_S[p];
                int cnt = min(g_degS[p], MAXDEG);
                float4 er4 = g_er4[v];
                float erv[NH] = {er4.x, er4.y, er4.z, er4.w};
                float mx[NH] = {-1e30f, -1e30f, -1e30f, -1e30f};
                for (int j = lane; j < cnt; j += 32) {
                    int s = g_bkt[(size_t)p * MAXDEG + j];
                    ssrc[w][j] = s;
                    float4 el4 = g_el4[s];
                    float es[4] = {el4.x, el4.y, el4.z, el4.w};
                    #pragma unroll
                    for (int h = 0; h < NH; h++) {
                        float x = es[h] + erv[h];
                        x = (x > 0.f) ? x : 0.2f * x;
                        ssc[w][j][h] = x;
                        mx[h] = fmaxf(mx[h], x);
                    }
                }
                #pragma unroll
                for (int h = 0; h < NH; h++) mx[h] = wredmax(mx[h]);
                __syncwarp();
                float sm[NH] = {0.f, 0.f, 0.f, 0.f};
                for (int j = lane; j < cnt; j += 32) {
                    #pragma unroll
                    for (int h = 0; h < NH; h++) {
                        float ex = expf(ssc[w][j][h] - mx[h]);
                        ssc[w][j][h] = ex;
                        sm[h] += ex;
                    }
                }
                #pragma unroll
                for (int h = 0; h < NH; h++) {
                    float s = wredsum(sm[h]);
                    if (lane == 0) sinv[w][h] = 1.f / s;
                }
            }
        }
        __syncthreads();
        // Phase B: 8 warps; warp w -> dst grp*2+(w>>2), quarter w&3 (128 dims)
        {
            int slot = w >> 2;
            int p = grp * 2 + slot;
            if (p < nS) {
                int quarter = w & 3;
                int cnt = min(g_degS[p], MAXDEG);
                float inv[NH];
                #pragma unroll
                for (int h = 0; h < NH; h++) inv[h] = sinv[slot][h];
                int dbase = quarter * 128 + lane * 4;   // 4 dims per lane
                float4 a[NH];
                #pragma unroll
                for (int h = 0; h < NH; h++) a[h] = make_float4(0, 0, 0, 0);
                for (int j = 0; j < cnt; j++) {
                    int s = ssrc[slot][j];
                    float wh[NH];
                    #pragma unroll
                    for (int h = 0; h < NH; h++) wh[h] = ssc[slot][j][h] * inv[h];
                    float4 f0 = *reinterpret_cast<const float4*>(X + (size_t)s * FD + dbase);
                    #pragma unroll
                    for (int h = 0; h < NH; h++) {
                        a[h].x = fmaf(wh[h], f0.x, a[h].x); a[h].y = fmaf(wh[h], f0.y, a[h].y);
                        a[h].z = fmaf(wh[h], f0.z, a[h].z); a[h].w = fmaf(wh[h], f0.w, a[h].w);
                    }
                }
                #pragma unroll
                for (int h = 0; h < NH; h++) {
                    float* zp = g_z + ((size_t)p * NH + h) * FD + dbase;
                    *reinterpret_cast<float4*>(zp) = a[h];
                }
            }
        }
        __syncthreads();
    }
}

// ---------------- layer-1 head-blocked GEMM + fused el1/er1 epilogue ----------------
constexpr int BN = 128, BK = 16, GT = 256;

__global__ __launch_bounds__(GT) void k_gemm1(const float* __restrict__ W,
                                              const float* __restrict__ bias) {
    constexpr int RPT = 4, BM = 64, ALD = 4, WLD = 8;
    __shared__ __align__(16) float As[2][BK][BM + 4];
    __shared__ __align__(16) float Ws[2][BK][BN + 4];
    float* C = g_h1p;
    int nRows = min(g_nS, MAX_S);
    int nRT = (nRows + BM - 1) / BM;
    int nTiles = nRT * (FD / BN);
    int tid = threadIdx.x;
    int tr = tid >> 4, tc = tid & 15;
    int wc = tid & 127, wk0 = tid >> 7;
    int woff[WLD];
    #pragma unroll
    for (int i = 0; i < WLD; i++) woff[i] = (wk0 + i * 2) * FD + wc;

    for (int t = blockIdx.x; t < nTiles; t += gridDim.x) {
        int rt = t >> 2, ct = t & 3;              // ct == head
        int rbase = rt * BM, cbase = ct * BN;
        const float* aptr[ALD];
        #pragma unroll
        for (int i = 0; i < ALD; i++) {
            int gr = rbase + tr + i * 16;
            aptr[i] = (gr < nRows) ? (g_z + ((size_t)gr * NH + ct) * FD) : nullptr;
        }
        const float* wbase = W + cbase;

        unsigned long long acc[RPT][4];
        #pragma unroll
        for (int r = 0; r < RPT; r++)
            #pragma unroll
            for (int c = 0; c < 4; c++) acc[r][c] = 0ull;

        float aReg[ALD], wReg[WLD];
        #pragma unroll
        for (int i = 0; i < ALD; i++) aReg[i] = aptr[i] ? aptr[i][tc] : 0.f;
        #pragma unroll
        for (int i = 0; i < WLD; i++) wReg[i] = wbase[woff[i]];
        #pragma unroll
        for (int i = 0; i < ALD; i++) As[0][tc][tr + i * 16] = aReg[i];
        #pragma unroll
        for (int i = 0; i < WLD; i++) Ws[0][wk0 + i * 2][wc] = wReg[i];
        __syncthreads();

        int buf = 0;
        for (int kc = 0; kc < FD; kc += BK) {
            bool more = (kc + BK) < FD;
            if (more) {
                int kn = kc + BK;
                #pragma unroll
                for (int i = 0; i < ALD; i++) aReg[i] = aptr[i] ? aptr[i][kn + tc] : 0.f;
                #pragma unroll
                for (int i = 0; i < WLD; i++) wReg[i] = wbase[(size_t)kn * FD + woff[i]];
            }
            #pragma unroll
            for (int kk = 0; kk < BK; kk++) {
                float4 av = *reinterpret_cast<const float4*>(&As[buf][kk][tr * 4]);
                unsigned long long ad[4] = {dup2(av.x), dup2(av.y), dup2(av.z), dup2(av.w)};
                ulonglong2 b0 = *reinterpret_cast<const ulonglong2*>(&Ws[buf][kk][tc * 8]);
                ulonglong2 b1 = *reinterpret_cast<const ulonglong2*>(&Ws[buf][kk][tc * 8 + 4]);
                unsigned long long bp[4] = {b0.x, b0.y, b1.x, b1.y};
                #pragma unroll
                for (int r = 0; r < RPT; r++)
                    #pragma unroll
                    for (int c = 0; c < 4; c++)
                        fma2(acc[r][c], ad[r], bp[c]);
            }
            __syncthreads();
            if (more) {
                #pragma unroll
                for (int i = 0; i < ALD; i++) As[buf ^ 1][tc][tr + i * 16] = aReg[i];
                #pragma unroll
                for (int i = 0; i < WLD; i++) Ws[buf ^ 1][wk0 + i * 2][wc] = wReg[i];
            }
            __syncthreads();
            buf ^= 1;
        }

        const float4* b4 = reinterpret_cast<const float4*>(bias + cbase + tc * 8);
        float4 bb0 = b4[0], bb1 = b4[1];
        float4 wl[8], wr[8];
        #pragma unroll
        for (int i = 0; i < 8; i++) {
            wl[i] = g_wl1_4[cbase + tc * 8 + i];
            wr[i] = g_wr1_4[cbase + tc * 8 + i];
        }
        #pragma unroll
        for (int r = 0; r < RPT; r++) {
            int gr = rbase + tr * 4 + r;
            if (gr < nRows) {
                float2 p0 = unpack2(acc[r][0]);
                float2 p1 = unpack2(acc[r][1]);
                float2 p2 = unpack2(acc[r][2]);
                float2 p3 = unpack2(acc[r][3]);
                float vals[8] = {eluf(p0.x + bb0.x), eluf(p0.y + bb0.y),
                                 eluf(p1.x + bb0.z), eluf(p1.y + bb0.w),
                                 eluf(p2.x + bb1.x), eluf(p2.y + bb1.y),
                                 eluf(p3.x + bb1.z), eluf(p3.y + bb1.w)};
                float* cp = C + (size_t)gr * FD + cbase + tc * 8;
                *reinterpret_cast<float4*>(cp)     = make_float4(vals[0], vals[1], vals[2], vals[3]);
                *reinterpret_cast<float4*>(cp + 4) = make_float4(vals[4], vals[5], vals[6], vals[7]);
                float l0 = 0, l1 = 0, l2 = 0, l3 = 0, r0 = 0, r1 = 0, r2 = 0, r3 = 0;
                #pragma unroll
                for (int i = 0; i < 8; i++) {
                    l0 = fmaf(vals[i], wl[i].x, l0); l1 = fmaf(vals[i], wl[i].y, l1);
                    l2 = fmaf(vals[i], wl[i].z, l2); l3 = fmaf(vals[i], wl[i].w, l3);
                    r0 = fmaf(vals[i], wr[i].x, r0); r1 = fmaf(vals[i], wr[i].y, r1);
                    r2 = fmaf(vals[i], wr[i].z, r2); r3 = fmaf(vals[i], wr[i].w, r3);
                }
                float* elp = reinterpret_cast<float*>(&g_el1_4[gr]);
                float* erp = reinterpret_cast<float*>(&g_er1_4[gr]);
                atomicAdd(elp + 0, l0); atomicAdd(elp + 1, l1);
                atomicAdd(elp + 2, l2); atomicAdd(elp + 3, l3);
                atomicAdd(erp + 0, r0); atomicAdd(erp + 1, r1);
                atomicAdd(erp + 2, r2); atomicAdd(erp + 3, r3);
            }
        }
    }
}

// ---------------- layer-2 per-head aggregation (bucket-based: ids are in S) ----------------
__global__ __launch_bounds__(512) void k_agg2(const int* __restrict__ ids, int nIds) {
    __shared__ int   sps[16][MAXDEG];
    __shared__ float ssc[16][MAXDEG][NH];
    int wslot = threadIdx.x >> 5, lane = threadIdx.x & 31;
    int item = blockIdx.x * 16 + wslot;
    if (item >= nIds * 2) return;
    int i = item >> 1, half = item & 1;
    int v = ids[i];
    int pv = g_posS[v];
    int cnt = min(g_degS[pv], MAXDEG);

    float4 er4 = g_er1_4[pv];
    float erv[NH] = {er4.x, er4.y, er4.z, er4.w};
    float mx[NH] = {-1e30f, -1e30f, -1e30f, -1e30f};
    for (int j = lane; j < cnt; j += 32) {
        int s = g_bkt[(size_t)pv * MAXDEG + j];
        int ps = g_posS[s];
        sps[wslot][j] = ps;
        float4 el4 = g_el1_4[ps];
        float es[4] = {el4.x, el4.y, el4.z, el4.w};
        #pragma unroll
        for (int h = 0; h < NH; h++) {
            float x = es[h] + erv[h];
            x = (x > 0.f) ? x : 0.2f * x;
            ssc[wslot][j][h] = x;
            mx[h] = fmaxf(mx[h], x);
        }
    }
    #pragma unroll
    for (int h = 0; h < NH; h++) mx[h] = wredmax(mx[h]);
    __syncwarp();
    float sm[NH] = {0.f, 0.f, 0.f, 0.f};
    for (int j = lane; j < cnt; j += 32) {
        #pragma unroll
        for (int h = 0; h < NH; h++) {
            float ex = expf(ssc[wslot][j][h] - mx[h]);
            ssc[wslot][j][h] = ex;
            sm[h] += ex;
        }
    }
    float inv[NH];
    #pragma unroll
    for (int h = 0; h < NH; h++) inv[h] = 1.f / wredsum(sm[h]);
    __syncwarp();

    int dbase = half * 256 + lane * 8;
    float4 a[NH][2];
    #pragma unroll
    for (int h = 0; h < NH; h++) { a[h][0] = make_float4(0, 0, 0, 0); a[h][1] = make_float4(0, 0, 0, 0); }
    for (int j = 0; j < cnt; j++) {
        int ps = sps[wslot][j];
        float wh[NH];
        #pragma unroll
        for (int h = 0; h < NH; h++) wh[h] = ssc[wslot][j][h] * inv[h];
        const float4* fp = reinterpret_cast<const float4*>(g_h1p + (size_t)ps * FD + dbase);
        float4 f0 = fp[0], f1 = fp[1];
        #pragma unroll
        for (int h = 0; h < NH; h++) {
            a[h][0].x = fmaf(wh[h], f0.x, a[h][0].x); a[h][0].y = fmaf(wh[h], f0.y, a[h][0].y);
            a[h][0].z = fmaf(wh[h], f0.z, a[h][0].z); a[h][0].w = fmaf(wh[h], f0.w, a[h][0].w);
            a[h][1].x = fmaf(wh[h], f1.x, a[h][1].x); a[h][1].y = fmaf(wh[h], f1.y, a[h][1].y);
            a[h][1].z = fmaf(wh[h], f1.z, a[h][1].z); a[h][1].w = fmaf(wh[h], f1.w, a[h][1].w);
        }
    }
    #pragma unroll
    for (int h = 0; h < NH; h++) {
        float* zp = g_z2 + ((size_t)i * NH + h) * FD + dbase;
        *reinterpret_cast<float4*>(zp)     = a[h][0];
        *reinterpret_cast<float4*>(zp + 4) = a[h][1];
    }
}

// ---------------- final ----------------
__global__ __launch_bounds__(256) void k_final(const float* __restrict__ W1,
                                               const float* __restrict__ bias1,
                                               const int* __restrict__ ids, int nIds,
                                               float* __restrict__ out) {
    int c = blockIdx.x * 32 + (threadIdx.x & 31);
    int hc = c >> 7;
    int rg = threadIdx.x >> 5;
    const float* wc = W1 + c;
    const float* z0 = g_z2 + ((size_t)rg * NH + hc) * FD;
    const float* z1 = g_z2 + ((size_t)(rg + 8) * NH + hc) * FD;
    float acc0 = 0.f, acc1 = 0.f;
    for (int k = 0; k < FD; k += 4) {
        float4 a = *reinterpret_cast<const float4*>(z0 + k);
        float4 b = *reinterpret_cast<const float4*>(z1 + k);
        float w0 = wc[(size_t)(k + 0) * FD];
        float w1 = wc[(size_t)(k + 1) * FD];
        float w2 = wc[(size_t)(k + 2) * FD];
        float w3 = wc[(size_t)(k + 3) * FD];
        acc0 = fmaf(a.x, w0, acc0); acc0 = fmaf(a.y, w1, acc0);
        acc0 = fmaf(a.z, w2, acc0); acc0 = fmaf(a.w, w3, acc0);
        acc1 = fmaf(b.x, w0, acc1); acc1 = fmaf(b.y, w1, acc1);
        acc1 = fmaf(b.z, w2, acc1); acc1 = fmaf(b.w, w3, acc1);
    }
    float bv = bias1[c];
    if (rg < nIds) {
        int pv = g_posS[ids[rg]];
        float x = acc0 + g_h1p[(size_t)pv * FD + c] + bv;
        out[(size_t)rg * FD + c] = tanhf(eluf(x));
    }
    int r2 = rg + 8;
    if (r2 < nIds) {
        int pv = g_posS[ids[r2]];
        float x = acc1 + g_h1p[(size_t)pv * FD + c] + bv;
        out[(size_t)r2 * FD + c] = tanhf(eluf(x));
    }
}

// ---------------- launch ----------------
extern "C" void kernel_launch(void* const* d_in, const int* in_sizes, int n_in,
                              void* d_out, int out_size) {
    const float* features = (const float*)d_in[0];
    const float* fc_w0    = (const float*)d_in[1];
    const float* attn_l0  = (const float*)d_in[2];
    const float* attn_r0  = (const float*)d_in[3];
    const float* bias0    = (const float*)d_in[4];
    const float* fc_w1    = (const float*)d_in[5];
    const float* attn_l1  = (const float*)d_in[6];
    const float* attn_r1  = (const float*)d_in[7];
    const float* bias1    = (const float*)d_in[8];
    const int*   src      = (const int*)d_in[9];
    const int*   dst      = (const int*)d_in[10];
    const int*   ids      = (const int*)d_in[11];
    int E    = in_sizes[9];
    int nIds = in_sizes[11];
    float* out = (float*)d_out;

    k_setup<<<128, 256>>>(fc_w0, attn_l0, attn_r0, fc_w1, attn_l1, attn_r1);
    k_scan_e2<<<1184, 256>>>(src, dst, ids, nIds, E);
    k_scan_e1<<<1184, 256>>>(src, dst, E);

    // layer 1
    k_eler0<<<1184, 256>>>(features);
    k_agg1<<<592, 256>>>(features);
    k_gemm1<<<36, GT>>>(fc_w0, bias0);

    // layer 2
    k_agg2<<<2, 512>>>(ids, nIds);
    k_final<<<16, 256>>>(fc_w1, bias1, ids, nIds, out);
}

// round 15
// speedup vs baseline: 1.0572x; 1.0572x over previous
#include <cuda_runtime.h>
#include <math.h>

#define NN 50000
#define FD 512
#define NH 4

constexpr int MAX_S  = 8192;
constexpr int MAX_U  = 262144;
constexpr int MAXDEG = 128;
constexpr int MAXIDS = 32;
constexpr int NMSK   = 1600;   // ceil(50000/32)

// ---------------- static device scratch ----------------
__device__ float4 g_el4[NN];
__device__ float4 g_er4[NN];
__device__ float  g_z[(size_t)MAX_S * NH * FD];
__device__ float  g_h1p[(size_t)MAX_S * FD];
__device__ float4 g_el1_4[MAX_S];
__device__ float4 g_er1_4[MAX_S];
__device__ float  g_z2[(size_t)MAXIDS * NH * FD];
__device__ float4 g_wl0_4[FD], g_wr0_4[FD], g_wl1_4[FD], g_wr1_4[FD];
__device__ float  g_wl0T[NH * FD], g_wr0T[NH * FD];   // transposed: [h][k]
__device__ unsigned g_mskS[NMSK], g_mskU[NMSK];
__device__ int g_S[MAX_S], g_posS[NN], g_degS[MAX_S];
__device__ int g_bkt[(size_t)MAX_S * MAXDEG];
__device__ int g_U[MAX_U];
__device__ int g_nS, g_nU;

// ---------------- helpers ----------------
__device__ __forceinline__ unsigned long long dup2(float a) {
    unsigned long long r;
    unsigned int ai = __float_as_uint(a);
    asm("mov.b64 %0, {%1, %1};" : "=l"(r) : "r"(ai));
    return r;
}
__device__ __forceinline__ void fma2(unsigned long long& d, unsigned long long a, unsigned long long b) {
    asm("fma.rn.f32x2 %0, %1, %2, %0;" : "+l"(d) : "l"(a), "l"(b));
}
__device__ __forceinline__ float2 unpack2(unsigned long long v) {
    float2 r;
    r.x = __uint_as_float((unsigned int)(v & 0xffffffffull));
    r.y = __uint_as_float((unsigned int)(v >> 32));
    return r;
}
__device__ __forceinline__ float wredsum(float x) {
    #pragma unroll
    for (int o = 16; o > 0; o >>= 1) x += __shfl_xor_sync(0xffffffffu, x, o);
    return x;
}
__device__ __forceinline__ float wredmax(float x) {
    #pragma unroll
    for (int o = 16; o > 0; o >>= 1) x = fmaxf(x, __shfl_xor_sync(0xffffffffu, x, o));
    return x;
}
__device__ __forceinline__ float eluf(float x) { return (x > 0.f) ? x : expm1f(x); }

// ---------------- setup: zero scratch + projected attention vectors (plain + transposed) ----------------
__global__ __launch_bounds__(256) void k_setup(const float* __restrict__ W0,
                                               const float* __restrict__ al0, const float* __restrict__ ar0,
                                               const float* __restrict__ W1,
                                               const float* __restrict__ al1, const float* __restrict__ ar1) {
    int gi = blockIdx.x * 256 + threadIdx.x;
    if (gi < MAX_S) {
        g_degS[gi] = 0;
        g_el1_4[gi] = make_float4(0, 0, 0, 0);
        g_er1_4[gi] = make_float4(0, 0, 0, 0);
    }
    if (gi < NMSK) { g_mskS[gi] = 0; g_mskU[gi] = 0; }
    if (gi == 0) { g_nS = 0; g_nU = 0; }

    int lane = threadIdx.x & 31;
    int w = gi >> 5;
    if (w >= FD) return;
    const float4* w0r = reinterpret_cast<const float4*>(W0 + (size_t)w * FD);
    const float4* w1r = reinterpret_cast<const float4*>(W1 + (size_t)w * FD);
    const float4* l0 = reinterpret_cast<const float4*>(al0);
    const float4* r0 = reinterpret_cast<const float4*>(ar0);
    const float4* l1 = reinterpret_cast<const float4*>(al1);
    const float4* r1 = reinterpret_cast<const float4*>(ar1);
    float sl0[NH], sr0[NH], sl1[NH], sr1[NH];
    #pragma unroll
    for (int h = 0; h < NH; h++) {
        float4 a0 = w0r[h * 32 + lane];
        float4 b0l = l0[h * 32 + lane];
        float4 b0r = r0[h * 32 + lane];
        sl0[h] = wredsum(a0.x * b0l.x + a0.y * b0l.y + a0.z * b0l.z + a0.w * b0l.w);
        sr0[h] = wredsum(a0.x * b0r.x + a0.y * b0r.y + a0.z * b0r.z + a0.w * b0r.w);
        float4 a1 = w1r[h * 32 + lane];
        float4 b1l = l1[h * 32 + lane];
        float4 b1r = r1[h * 32 + lane];
        sl1[h] = wredsum(a1.x * b1l.x + a1.y * b1l.y + a1.z * b1l.z + a1.w * b1l.w);
        sr1[h] = wredsum(a1.x * b1r.x + a1.y * b1r.y + a1.z * b1r.z + a1.w * b1r.w);
    }
    if (lane == 0) {
        g_wl0_4[w] = make_float4(sl0[0], sl0[1], sl0[2], sl0[3]);
        g_wr0_4[w] = make_float4(sr0[0], sr0[1], sr0[2], sr0[3]);
        g_wl1_4[w] = make_float4(sl1[0], sl1[1], sl1[2], sl1[3]);
        g_wr1_4[w] = make_float4(sr1[0], sr1[1], sr1[2], sr1[3]);
        #pragma unroll
        for (int h = 0; h < NH; h++) {
            g_wl0T[h * FD + w] = sl0[h];
            g_wr0T[h * FD + w] = sr0[h];
        }
    }
}

// ---------------- scan e2: edges into ids -> build S (smem id-bitmask) ----------------
__global__ __launch_bounds__(256) void k_scan_e2(const int* __restrict__ src, const int* __restrict__ dst,
                                                 const int* __restrict__ ids, int nIds, int E) {
    __shared__ unsigned smsk[NMSK];
    for (int i = threadIdx.x; i < NMSK; i += 256) smsk[i] = 0;
    __syncthreads();
    if (threadIdx.x < nIds) {
        int v = ids[threadIdx.x];
        atomicOr(&smsk[v >> 5], 1u << (v & 31));
    }
    __syncthreads();
    int i = blockIdx.x * blockDim.x + threadIdx.x;
    int stride = gridDim.x * blockDim.x;
    int E4 = E >> 2;
    const int4* d4 = reinterpret_cast<const int4*>(dst);
    auto proc = [&](int dd, int e) {
        if ((smsk[dd >> 5] >> (dd & 31)) & 1u) {
            int s = src[e];
            unsigned m = 1u << (s & 31);
            unsigned old = atomicOr(&g_mskS[s >> 5], m);
            if (!(old & m)) {
                int p = atomicAdd(&g_nS, 1);
                if (p < MAX_S) { g_S[p] = s; g_posS[s] = p; }
            }
        }
    };
    for (int q = i; q < E4; q += stride) {
        int4 d = d4[q];
        int e = q * 4;
        proc(d.x, e); proc(d.y, e + 1); proc(d.z, e + 2); proc(d.w, e + 3);
    }
    for (int e = E4 * 4 + i; e < E; e += stride) proc(dst[e], e);
}

// ---------------- scan e1: bucket edges into S (smem S-bitmask); build U ----------------
__global__ __launch_bounds__(256) void k_scan_e1(const int* __restrict__ src, const int* __restrict__ dst, int E) {
    __shared__ unsigned smsk[NMSK];
    for (int i = threadIdx.x; i < NMSK; i += 256) smsk[i] = g_mskS[i];
    __syncthreads();
    int i = blockIdx.x * blockDim.x + threadIdx.x;
    int stride = gridDim.x * blockDim.x;
    int E4 = E >> 2;
    const int4* d4 = reinterpret_cast<const int4*>(dst);
    auto proc = [&](int dd, int e) {
        if ((smsk[dd >> 5] >> (dd & 31)) & 1u) {
            int p = g_posS[dd];
            int s = src[e];
            int slot = atomicAdd(&g_degS[p], 1);
            if (slot < MAXDEG) g_bkt[(size_t)p * MAXDEG + slot] = s;
            unsigned m = 1u << (s & 31);
            if (!((g_mskU[s >> 5] >> (s & 31)) & 1u)) {
                unsigned old = atomicOr(&g_mskU[s >> 5], m);
                if (!(old & m)) {
                    int u = atomicAdd(&g_nU, 1);
                    if (u < MAX_U) g_U[u] = s;
                }
            }
        }
    };
    for (int q = i; q < E4; q += stride) {
        int4 d = d4[q];
        int e = q * 4;
        proc(d.x, e); proc(d.y, e + 1); proc(d.z, e + 2); proc(d.w, e + 3);
    }
    for (int e = E4 * 4 + i; e < E; e += stride) proc(dst[e], e);
}

// ---------------- el over U, er over S — conflict-free transposed smem tables ----------------
__global__ __launch_bounds__(256, 4) void k_eler0(const float* __restrict__ X) {
    __shared__ float swlT[NH * FD];   // 8KB, [h][k]
    __shared__ float swrT[NH * FD];   // 8KB
    for (int k = threadIdx.x; k < NH * FD; k += 256) { swlT[k] = g_wl0T[k]; swrT[k] = g_wr0T[k]; }
    __syncthreads();
    int lane = threadIdx.x & 31;
    int w = (blockIdx.x * blockDim.x + threadIdx.x) >> 5;
    int nw = (gridDim.x * blockDim.x) >> 5;
    int n = min(g_nU, MAX_U);
    for (int g = w; g < n; g += nw) {
        int v = g_U[g];
        const float4* xr = reinterpret_cast<const float4*>(X + (size_t)v * FD);
        float aL[NH] = {0, 0, 0, 0};
        #pragma unroll
        for (int i = 0; i < 4; i++) {
            float4 x4 = xr[i * 32 + lane];           // k-base = (i*32+lane)*4, coalesced
            int kb = (i * 32 + lane) * 4;
            #pragma unroll
            for (int h = 0; h < NH; h++) {
                float4 w4 = *reinterpret_cast<const float4*>(&swlT[h * FD + kb]);  // lane-stride 16B: conflict-free
                aL[h] += x4.x * w4.x + x4.y * w4.y + x4.z * w4.z + x4.w * w4.w;
            }
        }
        #pragma unroll
        for (int h = 0; h < NH; h++) aL[h] = wredsum(aL[h]);
        if (lane == 0) g_el4[v] = make_float4(aL[0], aL[1], aL[2], aL[3]);
    }
    // er pass: only S nodes need er (they are the dsts)
    int nS = min(g_nS, MAX_S);
    for (int g = w; g < nS; g += nw) {
        int v = g_S[g];
        const float4* xr = reinterpret_cast<const float4*>(X + (size_t)v * FD);
        float aR[NH] = {0, 0, 0, 0};
        #pragma unroll
        for (int i = 0; i < 4; i++) {
            float4 x4 = xr[i * 32 + lane];
            int kb = (i * 32 + lane) * 4;
            #pragma unroll
            for (int h = 0; h < NH; h++) {
                float4 w4 = *reinterpret_cast<const float4*>(&swrT[h * FD + kb]);
                aR[h] += x4.x * w4.x + x4.y * w4.y + x4.z * w4.z + x4.w * w4.w;
            }
        }
        #pragma unroll
        for (int h = 0; h < NH; h++) aR[h] = wredsum(aR[h]);
        if (lane == 0) g_er4[v] = make_float4(aR[0], aR[1], aR[2], aR[3]);
    }
}

// ---------------- layer-1 per-head aggregation; block = 4 dsts, scores shared ----------------
__global__ __launch_bounds__(256, 4) void k_agg1(const float* __restrict__ X) {
    __shared__ int   ssrc[4][MAXDEG];
    __shared__ float ssc[4][MAXDEG][NH];
    __shared__ float sinv[4][NH];
    int w = threadIdx.x >> 5, lane = threadIdx.x & 31;
    int nS = min(g_nS, MAX_S);
    int nGrp = (nS + 3) >> 2;
    for (int grp = blockIdx.x; grp < nGrp; grp += gridDim.x) {
        if (w < 4) {
            int p = grp * 4 + w;
            if (p < nS) {
                int v = g_S[p];
                int cnt = min(g_degS[p], MAXDEG);
                float4 er4 = g_er4[v];
                float erv[NH] = {er4.x, er4.y, er4.z, er4.w};
                float mx[NH] = {-1e30f, -1e30f, -1e30f, -1e30f};
                for (int j = lane; j < cnt; j += 32) {
                    int s = g_bkt[(size_t)p * MAXDEG + j];
                    ssrc[w][j] = s;
                    float4 el4 = g_el4[s];
                    float es[4] = {el4.x, el4.y, el4.z, el4.w};
                    #pragma unroll
                    for (int h = 0; h < NH; h++) {
                        float x = es[h] + erv[h];
                        x = (x > 0.f) ? x : 0.2f * x;
                        ssc[w][j][h] = x;
                        mx[h] = fmaxf(mx[h], x);
                    }
                }
                #pragma unroll
                for (int h = 0; h < NH; h++) mx[h] = wredmax(mx[h]);
                __syncwarp();
                float sm[NH] = {0.f, 0.f, 0.f, 0.f};
                for (int j = lane; j < cnt; j += 32) {
                    #pragma unroll
                    for (int h = 0; h < NH; h++) {
                        float ex = expf(ssc[w][j][h] - mx[h]);
                        ssc[w][j][h] = ex;
                        sm[h] += ex;
                    }
                }
                #pragma unroll
                for (int h = 0; h < NH; h++) {
                    float s = wredsum(sm[h]);
                    if (lane == 0) sinv[w][h] = 1.f / s;
                }
            }
        }
        __syncthreads();
        {
            int slot = w >> 1;
            int p = grp * 4 + slot;
            if (p < nS) {
                int half = w & 1;
                int cnt = min(g_degS[p], MAXDEG);
                float inv[NH];
                #pragma unroll
                for (int h = 0; h < NH; h++) inv[h] = sinv[slot][h];
                int dbase = half * 256 + lane * 8;
                float4 a[NH][2];
                #pragma unroll
                for (int h = 0; h < NH; h++) { a[h][0] = make_float4(0, 0, 0, 0); a[h][1] = make_float4(0, 0, 0, 0); }
                for (int j = 0; j < cnt; j++) {
                    int s = ssrc[slot][j];
                    float wh[NH];
                    #pragma unroll
                    for (int h = 0; h < NH; h++) wh[h] = ssc[slot][j][h] * inv[h];
                    const float4* xp = reinterpret_cast<const float4*>(X + (size_t)s * FD + dbase);
                    float4 f0 = xp[0], f1 = xp[1];
                    #pragma unroll
                    for (int h = 0; h < NH; h++) {
                        a[h][0].x = fmaf(wh[h], f0.x, a[h][0].x); a[h][0].y = fmaf(wh[h], f0.y, a[h][0].y);
                        a[h][0].z = fmaf(wh[h], f0.z, a[h][0].z); a[h][0].w = fmaf(wh[h], f0.w, a[h][0].w);
                        a[h][1].x = fmaf(wh[h], f1.x, a[h][1].x); a[h][1].y = fmaf(wh[h], f1.y, a[h][1].y);
                        a[h][1].z = fmaf(wh[h], f1.z, a[h][1].z); a[h][1].w = fmaf(wh[h], f1.w, a[h][1].w);
                    }
                }
                #pragma unroll
                for (int h = 0; h < NH; h++) {
                    float* zp = g_z + ((size_t)p * NH + h) * FD + dbase;
                    *reinterpret_cast<float4*>(zp)     = a[h][0];
                    *reinterpret_cast<float4*>(zp + 4) = a[h][1];
                }
            }
        }
        __syncthreads();
    }
}

// ---------------- layer-1 head-blocked GEMM + fused el1/er1 epilogue ----------------
constexpr int BN = 128, BK = 16, GT = 256;

__global__ __launch_bounds__(GT) void k_gemm1(const float* __restrict__ W,
                                              const float* __restrict__ bias) {
    constexpr int RPT = 4, BM = 64, ALD = 4, WLD = 8;
    __shared__ __align__(16) float As[2][BK][BM + 4];
    __shared__ __align__(16) float Ws[2][BK][BN + 4];
    float* C = g_h1p;
    int nRows = min(g_nS, MAX_S);
    int nRT = (nRows + BM - 1) / BM;
    int nTiles = nRT * (FD / BN);
    int tid = threadIdx.x;
    int tr = tid >> 4, tc = tid & 15;
    int wc = tid & 127, wk0 = tid >> 7;
    int woff[WLD];
    #pragma unroll
    for (int i = 0; i < WLD; i++) woff[i] = (wk0 + i * 2) * FD + wc;

    for (int t = blockIdx.x; t < nTiles; t += gridDim.x) {
        int rt = t >> 2, ct = t & 3;              // ct == head
        int rbase = rt * BM, cbase = ct * BN;
        const float* aptr[ALD];
        #pragma unroll
        for (int i = 0; i < ALD; i++) {
            int gr = rbase + tr + i * 16;
            aptr[i] = (gr < nRows) ? (g_z + ((size_t)gr * NH + ct) * FD) : nullptr;
        }
        const float* wbase = W + cbase;

        unsigned long long acc[RPT][4];
        #pragma unroll
        for (int r = 0; r < RPT; r++)
            #pragma unroll
            for (int c = 0; c < 4; c++) acc[r][c] = 0ull;

        float aReg[ALD], wReg[WLD];
        #pragma unroll
        for (int i = 0; i < ALD; i++) aReg[i] = aptr[i] ? aptr[i][tc] : 0.f;
        #pragma unroll
        for (int i = 0; i < WLD; i++) wReg[i] = wbase[woff[i]];
        #pragma unroll
        for (int i = 0; i < ALD; i++) As[0][tc][tr + i * 16] = aReg[i];
        #pragma unroll
        for (int i = 0; i < WLD; i++) Ws[0][wk0 + i * 2][wc] = wReg[i];
        __syncthreads();

        int buf = 0;
        for (int kc = 0; kc < FD; kc += BK) {
            bool more = (kc + BK) < FD;
            if (more) {
                int kn = kc + BK;
                #pragma unroll
                for (int i = 0; i < ALD; i++) aReg[i] = aptr[i] ? aptr[i][kn + tc] : 0.f;
                #pragma unroll
                for (int i = 0; i < WLD; i++) wReg[i] = wbase[(size_t)kn * FD + woff[i]];
            }
            #pragma unroll
            for (int kk = 0; kk < BK; kk++) {
                float4 av = *reinterpret_cast<const float4*>(&As[buf][kk][tr * 4]);
                unsigned long long ad[4] = {dup2(av.x), dup2(av.y), dup2(av.z), dup2(av.w)};
                ulonglong2 b0 = *reinterpret_cast<const ulonglong2*>(&Ws[buf][kk][tc * 8]);
                ulonglong2 b1 = *reinterpret_cast<const ulonglong2*>(&Ws[buf][kk][tc * 8 + 4]);
                unsigned long long bp[4] = {b0.x, b0.y, b1.x, b1.y};
                #pragma unroll
                for (int r = 0; r < RPT; r++)
                    #pragma unroll
                    for (int c = 0; c < 4; c++)
                        fma2(acc[r][c], ad[r], bp[c]);
            }
            __syncthreads();
            if (more) {
                #pragma unroll
                for (int i = 0; i < ALD; i++) As[buf ^ 1][tc][tr + i * 16] = aReg[i];
                #pragma unroll
                for (int i = 0; i < WLD; i++) Ws[buf ^ 1][wk0 + i * 2][wc] = wReg[i];
            }
            __syncthreads();
            buf ^= 1;
        }

        const float4* b4 = reinterpret_cast<const float4*>(bias + cbase + tc * 8);
        float4 bb0 = b4[0], bb1 = b4[1];
        float4 wl[8], wr[8];
        #pragma unroll
        for (int i = 0; i < 8; i++) {
            wl[i] = g_wl1_4[cbase + tc * 8 + i];
            wr[i] = g_wr1_4[cbase + tc * 8 + i];
        }
        #pragma unroll
        for (int r = 0; r < RPT; r++) {
            int gr = rbase + tr * 4 + r;
            if (gr < nRows) {
                float2 p0 = unpack2(acc[r][0]);
                float2 p1 = unpack2(acc[r][1]);
                float2 p2 = unpack2(acc[r][2]);
                float2 p3 = unpack2(acc[r][3]);
                float vals[8] = {eluf(p0.x + bb0.x), eluf(p0.y + bb0.y),
                                 eluf(p1.x + bb0.z), eluf(p1.y + bb0.w),
                                 eluf(p2.x + bb1.x), eluf(p2.y + bb1.y),
                                 eluf(p3.x + bb1.z), eluf(p3.y + bb1.w)};
                float* cp = C + (size_t)gr * FD + cbase + tc * 8;
                *reinterpret_cast<float4*>(cp)     = make_float4(vals[0], vals[1], vals[2], vals[3]);
                *reinterpret_cast<float4*>(cp + 4) = make_float4(vals[4], vals[5], vals[6], vals[7]);
                float l0 = 0, l1 = 0, l2 = 0, l3 = 0, r0 = 0, r1 = 0, r2 = 0, r3 = 0;
                #pragma unroll
                for (int i = 0; i < 8; i++) {
                    l0 = fmaf(vals[i], wl[i].x, l0); l1 = fmaf(vals[i], wl[i].y, l1);
                    l2 = fmaf(vals[i], wl[i].z, l2); l3 = fmaf(vals[i], wl[i].w, l3);
                    r0 = fmaf(vals[i], wr[i].x, r0); r1 = fmaf(vals[i], wr[i].y, r1);
                    r2 = fmaf(vals[i], wr[i].z, r2); r3 = fmaf(vals[i], wr[i].w, r3);
                }
                float* elp = reinterpret_cast<float*>(&g_el1_4[gr]);
                float* erp = reinterpret_cast<float*>(&g_er1_4[gr]);
                atomicAdd(elp + 0, l0); atomicAdd(elp + 1, l1);
                atomicAdd(elp + 2, l2); atomicAdd(elp + 3, l3);
                atomicAdd(erp + 0, r0); atomicAdd(erp + 1, r1);
                atomicAdd(erp + 2, r2); atomicAdd(erp + 3, r3);
            }
        }
    }
}

// ---------------- layer-2 per-head aggregation (bucket-based: ids are in S) ----------------
__global__ __launch_bounds__(512) void k_agg2(const int* __restrict__ ids, int nIds) {
    __shared__ int   sps[16][MAXDEG];
    __shared__ float ssc[16][MAXDEG][NH];
    int wslot = threadIdx.x >> 5, lane = threadIdx.x & 31;
    int item = blockIdx.x * 16 + wslot;
    if (item >= nIds * 2) return;
    int i = item >> 1, half = item & 1;
    int v = ids[i];
    int pv = g_posS[v];
    int cnt = min(g_degS[pv], MAXDEG);

    float4 er4 = g_er1_4[pv];
    float erv[NH] = {er4.x, er4.y, er4.z, er4.w};
    float mx[NH] = {-1e30f, -1e30f, -1e30f, -1e30f};
    for (int j = lane; j < cnt; j += 32) {
        int s = g_bkt[(size_t)pv * MAXDEG + j];
        int ps = g_posS[s];
        sps[wslot][j] = ps;
        float4 el4 = g_el1_4[ps];
        float es[4] = {el4.x, el4.y, el4.z, el4.w};
        #pragma unroll
        for (int h = 0; h < NH; h++) {
            float x = es[h] + erv[h];
            x = (x > 0.f) ? x : 0.2f * x;
            ssc[wslot][j][h] = x;
            mx[h] = fmaxf(mx[h], x);
        }
    }
    #pragma unroll
    for (int h = 0; h < NH; h++) mx[h] = wredmax(mx[h]);
    __syncwarp();
    float sm[NH] = {0.f, 0.f, 0.f, 0.f};
    for (int j = lane; j < cnt; j += 32) {
        #pragma unroll
        for (int h = 0; h < NH; h++) {
            float ex = expf(ssc[wslot][j][h] - mx[h]);
            ssc[wslot][j][h] = ex;
            sm[h] += ex;
        }
    }
    float inv[NH];
    #pragma unroll
    for (int h = 0; h < NH; h++) inv[h] = 1.f / wredsum(sm[h]);
    __syncwarp();

    int dbase = half * 256 + lane * 8;
    float4 a[NH][2];
    #pragma unroll
    for (int h = 0; h < NH; h++) { a[h][0] = make_float4(0, 0, 0, 0); a[h][1] = make_float4(0, 0, 0, 0); }
    for (int j = 0; j < cnt; j++) {
        int ps = sps[wslot][j];
        float wh[NH];
        #pragma unroll
        for (int h = 0; h < NH; h++) wh[h] = ssc[wslot][j][h] * inv[h];
        const float4* fp = reinterpret_cast<const float4*>(g_h1p + (size_t)ps * FD + dbase);
        float4 f0 = fp[0], f1 = fp[1];
        #pragma unroll
        for (int h = 0; h < NH; h++) {
            a[h][0].x = fmaf(wh[h], f0.x, a[h][0].x); a[h][0].y = fmaf(wh[h], f0.y, a[h][0].y);
            a[h][0].z = fmaf(wh[h], f0.z, a[h][0].z); a[h][0].w = fmaf(wh[h], f0.w, a[h][0].w);
            a[h][1].x = fmaf(wh[h], f1.x, a[h][1].x); a[h][1].y = fmaf(wh[h], f1.y, a[h][1].y);
            a[h][1].z = fmaf(wh[h], f1.z, a[h][1].z); a[h][1].w = fmaf(wh[h], f1.w, a[h][1].w);
        }
    }
    #pragma unroll
    for (int h = 0; h < NH; h++) {
        float* zp = g_z2 + ((size_t)i * NH + h) * FD + dbase;
        *reinterpret_cast<float4*>(zp)     = a[h][0];
        *reinterpret_cast<float4*>(zp + 4) = a[h][1];
    }
}

// ---------------- final ----------------
__global__ __launch_bounds__(256) void k_final(const float* __restrict__ W1,
                                               const float* __restrict__ bias1,
                                               const int* __restrict__ ids, int nIds,
                                               float* __restrict__ out) {
    int c = blockIdx.x * 32 + (threadIdx.x & 31);
    int hc = c >> 7;
    int rg = threadIdx.x >> 5;
    const float* wc = W1 + c;
    const float* z0 = g_z2 + ((size_t)rg * NH + hc) * FD;
    const float* z1 = g_z2 + ((size_t)(rg + 8) * NH + hc) * FD;
    float acc0 = 0.f, acc1 = 0.f;
    for (int k = 0; k < FD; k += 4) {
        float4 a = *reinterpret_cast<const float4*>(z0 + k);
        float4 b = *reinterpret_cast<const float4*>(z1 + k);
        float w0 = wc[(size_t)(k + 0) * FD];
        float w1 = wc[(size_t)(k + 1) * FD];
        float w2 = wc[(size_t)(k + 2) * FD];
        float w3 = wc[(size_t)(k + 3) * FD];
        acc0 = fmaf(a.x, w0, acc0); acc0 = fmaf(a.y, w1, acc0);
        acc0 = fmaf(a.z, w2, acc0); acc0 = fmaf(a.w, w3, acc0);
        acc1 = fmaf(b.x, w0, acc1); acc1 = fmaf(b.y, w1, acc1);
        acc1 = fmaf(b.z, w2, acc1); acc1 = fmaf(b.w, w3, acc1);
    }
    float bv = bias1[c];
    if (rg < nIds) {
        int pv = g_posS[ids[rg]];
        float x = acc0 + g_h1p[(size_t)pv * FD + c] + bv;
        out[(size_t)rg * FD + c] = tanhf(eluf(x));
    }
    int r2 = rg + 8;
    if (r2 < nIds) {
        int pv = g_posS[ids[r2]];
        float x = acc1 + g_h1p[(size_t)pv * FD + c] + bv;
        out[(size_t)r2 * FD + c] = tanhf(eluf(x));
    }
}

// ---------------- launch ----------------
extern "C" void kernel_launch(void* const* d_in, const int* in_sizes, int n_in,
                              void* d_out, int out_size) {
    const float* features = (const float*)d_in[0];
    const float* fc_w0    = (const float*)d_in[1];
    const float* attn_l0  = (const float*)d_in[2];
    const float* attn_r0  = (const float*)d_in[3];
    const float* bias0    = (const float*)d_in[4];
    const float* fc_w1    = (const float*)d_in[5];
    const float* attn_l1  = (const float*)d_in[6];
    const float* attn_r1  = (const float*)d_in[7];
    const float* bias1    = (const float*)d_in[8];
    const int*   src      = (const int*)d_in[9];
    const int*   dst      = (const int*)d_in[10];
    const int*   ids      = (const int*)d_in[11];
    int E    = in_sizes[9];
    int nIds = in_sizes[11];
    float* out = (float*)d_out;

    k_setup<<<128, 256>>>(fc_w0, attn_l0, attn_r0, fc_w1, attn_l1, attn_r1);
    k_scan_e2<<<1184, 256>>>(src, dst, ids, nIds, E);
    k_scan_e1<<<1184, 256>>>(src, dst, E);

    // layer 1
    k_eler0<<<592, 256>>>(features);
    k_agg1<<<296, 256>>>(features);
    k_gemm1<<<36, GT>>>(fc_w0, bias0);

    // layer 2
    k_agg2<<<2, 512>>>(ids, nIds);
    k_final<<<16, 256>>>(fc_w1, bias1, ids, nIds, out);
}

// round 16
// speedup vs baseline: 1.1848x; 1.1207x over previous
#include <cuda_runtime.h>
#include <math.h>

#define NN 50000
#define FD 512
#define NH 4

constexpr int MAX_S  = 8192;
constexpr int MAX_U  = 262144;
constexpr int MAXDEG = 128;
constexpr int MAXIDS = 32;
constexpr int NMSK   = 1600;   // ceil(50000/32)

// ---------------- static device scratch ----------------
__device__ float4 g_el4[NN];
__device__ float4 g_er4[NN];
__device__ float  g_z[(size_t)MAX_S * NH * FD];
__device__ float  g_h1p[(size_t)MAX_S * FD];
__device__ float4 g_el1_4[MAX_S];
__device__ float4 g_er1_4[MAX_S];
__device__ float  g_z2[(size_t)MAXIDS * NH * FD];
__device__ float4 g_wl0_4[FD], g_wr0_4[FD], g_wl1_4[FD], g_wr1_4[FD];
__device__ float  g_wl0T[NH * FD], g_wr0T[NH * FD];   // transposed: [h][k]
__device__ unsigned g_mskS[NMSK], g_mskU[NMSK];
__device__ int g_S[MAX_S], g_posS[NN], g_degS[MAX_S];
__device__ int g_bkt[(size_t)MAX_S * MAXDEG];
__device__ int g_U[MAX_U];
__device__ int g_nS, g_nU;

// ---------------- helpers ----------------
__device__ __forceinline__ unsigned long long dup2(float a) {
    unsigned long long r;
    unsigned int ai = __float_as_uint(a);
    asm("mov.b64 %0, {%1, %1};" : "=l"(r) : "r"(ai));
    return r;
}
__device__ __forceinline__ void fma2(unsigned long long& d, unsigned long long a, unsigned long long b) {
    asm("fma.rn.f32x2 %0, %1, %2, %0;" : "+l"(d) : "l"(a), "l"(b));
}
__device__ __forceinline__ float2 unpack2(unsigned long long v) {
    float2 r;
    r.x = __uint_as_float((unsigned int)(v & 0xffffffffull));
    r.y = __uint_as_float((unsigned int)(v >> 32));
    return r;
}
__device__ __forceinline__ float wredsum(float x) {
    #pragma unroll
    for (int o = 16; o > 0; o >>= 1) x += __shfl_xor_sync(0xffffffffu, x, o);
    return x;
}
__device__ __forceinline__ float wredmax(float x) {
    #pragma unroll
    for (int o = 16; o > 0; o >>= 1) x = fmaxf(x, __shfl_xor_sync(0xffffffffu, x, o));
    return x;
}
__device__ __forceinline__ float eluf(float x) { return (x > 0.f) ? x : expm1f(x); }

// ---------------- setup: zero scratch + projected attention vectors (plain + transposed) ----------------
__global__ __launch_bounds__(256) void k_setup(const float* __restrict__ W0,
                                               const float* __restrict__ al0, const float* __restrict__ ar0,
                                               const float* __restrict__ W1,
                                               const float* __restrict__ al1, const float* __restrict__ ar1) {
    int gi = blockIdx.x * 256 + threadIdx.x;
    if (gi < MAX_S) {
        g_degS[gi] = 0;
        g_el1_4[gi] = make_float4(0, 0, 0, 0);
        g_er1_4[gi] = make_float4(0, 0, 0, 0);
    }
    if (gi < NMSK) { g_mskS[gi] = 0; g_mskU[gi] = 0; }
    if (gi == 0) { g_nS = 0; g_nU = 0; }

    int lane = threadIdx.x & 31;
    int w = gi >> 5;
    if (w >= FD) return;
    const float4* w0r = reinterpret_cast<const float4*>(W0 + (size_t)w * FD);
    const float4* w1r = reinterpret_cast<const float4*>(W1 + (size_t)w * FD);
    const float4* l0 = reinterpret_cast<const float4*>(al0);
    const float4* r0 = reinterpret_cast<const float4*>(ar0);
    const float4* l1 = reinterpret_cast<const float4*>(al1);
    const float4* r1 = reinterpret_cast<const float4*>(ar1);
    float sl0[NH], sr0[NH], sl1[NH], sr1[NH];
    #pragma unroll
    for (int h = 0; h < NH; h++) {
        float4 a0 = w0r[h * 32 + lane];
        float4 b0l = l0[h * 32 + lane];
        float4 b0r = r0[h * 32 + lane];
        sl0[h] = wredsum(a0.x * b0l.x + a0.y * b0l.y + a0.z * b0l.z + a0.w * b0l.w);
        sr0[h] = wredsum(a0.x * b0r.x + a0.y * b0r.y + a0.z * b0r.z + a0.w * b0r.w);
        float4 a1 = w1r[h * 32 + lane];
        float4 b1l = l1[h * 32 + lane];
        float4 b1r = r1[h * 32 + lane];
        sl1[h] = wredsum(a1.x * b1l.x + a1.y * b1l.y + a1.z * b1l.z + a1.w * b1l.w);
        sr1[h] = wredsum(a1.x * b1r.x + a1.y * b1r.y + a1.z * b1r.z + a1.w * b1r.w);
    }
    if (lane == 0) {
        g_wl0_4[w] = make_float4(sl0[0], sl0[1], sl0[2], sl0[3]);
        g_wr0_4[w] = make_float4(sr0[0], sr0[1], sr0[2], sr0[3]);
        g_wl1_4[w] = make_float4(sl1[0], sl1[1], sl1[2], sl1[3]);
        g_wr1_4[w] = make_float4(sr1[0], sr1[1], sr1[2], sr1[3]);
        #pragma unroll
        for (int h = 0; h < NH; h++) {
            g_wl0T[h * FD + w] = sl0[h];
            g_wr0T[h * FD + w] = sr0[h];
        }
    }
}

// ---------------- scan e2: edges into ids -> build S (smem id-bitmask) ----------------
__global__ __launch_bounds__(256) void k_scan_e2(const int* __restrict__ src, const int* __restrict__ dst,
                                                 const int* __restrict__ ids, int nIds, int E) {
    __shared__ unsigned smsk[NMSK];
    for (int i = threadIdx.x; i < NMSK; i += 256) smsk[i] = 0;
    __syncthreads();
    if (threadIdx.x < nIds) {
        int v = ids[threadIdx.x];
        atomicOr(&smsk[v >> 5], 1u << (v & 31));
    }
    __syncthreads();
    int i = blockIdx.x * blockDim.x + threadIdx.x;
    int stride = gridDim.x * blockDim.x;
    int E4 = E >> 2;
    const int4* d4 = reinterpret_cast<const int4*>(dst);
    auto proc = [&](int dd, int e) {
        if ((smsk[dd >> 5] >> (dd & 31)) & 1u) {
            int s = src[e];
            unsigned m = 1u << (s & 31);
            unsigned old = atomicOr(&g_mskS[s >> 5], m);
            if (!(old & m)) {
                int p = atomicAdd(&g_nS, 1);
                if (p < MAX_S) { g_S[p] = s; g_posS[s] = p; }
            }
        }
    };
    for (int q = i; q < E4; q += stride) {
        int4 d = d4[q];
        int e = q * 4;
        proc(d.x, e); proc(d.y, e + 1); proc(d.z, e + 2); proc(d.w, e + 3);
    }
    for (int e = E4 * 4 + i; e < E; e += stride) proc(dst[e], e);
}

// ---------------- scan e1: bucket edges into S (smem S-bitmask); build U ----------------
__global__ __launch_bounds__(256) void k_scan_e1(const int* __restrict__ src, const int* __restrict__ dst, int E) {
    __shared__ unsigned smsk[NMSK];
    for (int i = threadIdx.x; i < NMSK; i += 256) smsk[i] = g_mskS[i];
    __syncthreads();
    int i = blockIdx.x * blockDim.x + threadIdx.x;
    int stride = gridDim.x * blockDim.x;
    int E4 = E >> 2;
    const int4* d4 = reinterpret_cast<const int4*>(dst);
    auto proc = [&](int dd, int e) {
        if ((smsk[dd >> 5] >> (dd & 31)) & 1u) {
            int p = g_posS[dd];
            int s = src[e];
            int slot = atomicAdd(&g_degS[p], 1);
            if (slot < MAXDEG) g_bkt[(size_t)p * MAXDEG + slot] = s;
            unsigned m = 1u << (s & 31);
            if (!((g_mskU[s >> 5] >> (s & 31)) & 1u)) {
                unsigned old = atomicOr(&g_mskU[s >> 5], m);
                if (!(old & m)) {
                    int u = atomicAdd(&g_nU, 1);
                    if (u < MAX_U) g_U[u] = s;
                }
            }
        }
    };
    for (int q = i; q < E4; q += stride) {
        int4 d = d4[q];
        int e = q * 4;
        proc(d.x, e); proc(d.y, e + 1); proc(d.z, e + 2); proc(d.w, e + 3);
    }
    for (int e = E4 * 4 + i; e < E; e += stride) proc(dst[e], e);
}

// ---------------- el over U (2 nodes/warp-iter), er over S — conflict-free transposed tables ----------------
__global__ __launch_bounds__(256, 4) void k_eler0(const float* __restrict__ X) {
    __shared__ float swlT[NH * FD];   // 8KB, [h][k]
    __shared__ float swrT[NH * FD];   // 8KB
    for (int k = threadIdx.x; k < NH * FD; k += 256) { swlT[k] = g_wl0T[k]; swrT[k] = g_wr0T[k]; }
    __syncthreads();
    int lane = threadIdx.x & 31;
    int w = (blockIdx.x * blockDim.x + threadIdx.x) >> 5;
    int nw = (gridDim.x * blockDim.x) >> 5;
    int n = min(g_nU, MAX_U);
    for (int g = w * 2; g < n; g += nw * 2) {
        int v0 = g_U[g];
        bool two = (g + 1) < n;
        int v1 = two ? g_U[g + 1] : v0;
        const float4* x0 = reinterpret_cast<const float4*>(X + (size_t)v0 * FD);
        const float4* x1 = reinterpret_cast<const float4*>(X + (size_t)v1 * FD);
        float a0[NH] = {0, 0, 0, 0}, a1[NH] = {0, 0, 0, 0};
        #pragma unroll
        for (int i = 0; i < 4; i++) {
            float4 p = x0[i * 32 + lane];
            float4 q = x1[i * 32 + lane];
            int kb = (i * 32 + lane) * 4;
            #pragma unroll
            for (int h = 0; h < NH; h++) {
                float4 w4 = *reinterpret_cast<const float4*>(&swlT[h * FD + kb]);
                a0[h] += p.x * w4.x + p.y * w4.y + p.z * w4.z + p.w * w4.w;
                a1[h] += q.x * w4.x + q.y * w4.y + q.z * w4.z + q.w * w4.w;
            }
        }
        #pragma unroll
        for (int h = 0; h < NH; h++) { a0[h] = wredsum(a0[h]); a1[h] = wredsum(a1[h]); }
        if (lane == 0) {
            g_el4[v0] = make_float4(a0[0], a0[1], a0[2], a0[3]);
            if (two) g_el4[v1] = make_float4(a1[0], a1[1], a1[2], a1[3]);
        }
    }
    // er pass: only S nodes need er (they are the dsts)
    int nS = min(g_nS, MAX_S);
    for (int g = w; g < nS; g += nw) {
        int v = g_S[g];
        const float4* xr = reinterpret_cast<const float4*>(X + (size_t)v * FD);
        float aR[NH] = {0, 0, 0, 0};
        #pragma unroll
        for (int i = 0; i < 4; i++) {
            float4 x4 = xr[i * 32 + lane];
            int kb = (i * 32 + lane) * 4;
            #pragma unroll
            for (int h = 0; h < NH; h++) {
                float4 w4 = *reinterpret_cast<const float4*>(&swrT[h * FD + kb]);
                aR[h] += x4.x * w4.x + x4.y * w4.y + x4.z * w4.z + x4.w * w4.w;
            }
        }
        #pragma unroll
        for (int h = 0; h < NH; h++) aR[h] = wredsum(aR[h]);
        if (lane == 0) g_er4[v] = make_float4(aR[0], aR[1], aR[2], aR[3]);
    }
}

// ---------------- layer-1 per-head aggregation; block = 4 dsts, scores shared ----------------
__global__ __launch_bounds__(256) void k_agg1(const float* __restrict__ X) {
    __shared__ int   ssrc[4][MAXDEG];
    __shared__ float ssc[4][MAXDEG][NH];
    __shared__ float sinv[4][NH];
    int w = threadIdx.x >> 5, lane = threadIdx.x & 31;
    int nS = min(g_nS, MAX_S);
    int nGrp = (nS + 3) >> 2;
    for (int grp = blockIdx.x; grp < nGrp; grp += gridDim.x) {
        if (w < 4) {
            int p = grp * 4 + w;
            if (p < nS) {
                int v = g_S[p];
                int cnt = min(g_degS[p], MAXDEG);
                float4 er4 = g_er4[v];
                float erv[NH] = {er4.x, er4.y, er4.z, er4.w};
                float mx[NH] = {-1e30f, -1e30f, -1e30f, -1e30f};
                for (int j = lane; j < cnt; j += 32) {
                    int s = g_bkt[(size_t)p * MAXDEG + j];
                    ssrc[w][j] = s;
                    float4 el4 = g_el4[s];
                    float es[4] = {el4.x, el4.y, el4.z, el4.w};
                    #pragma unroll
                    for (int h = 0; h < NH; h++) {
                        float x = es[h] + erv[h];
                        x = (x > 0.f) ? x : 0.2f * x;
                        ssc[w][j][h] = x;
                        mx[h] = fmaxf(mx[h], x);
                    }
                }
                #pragma unroll
                for (int h = 0; h < NH; h++) mx[h] = wredmax(mx[h]);
                __syncwarp();
                float sm[NH] = {0.f, 0.f, 0.f, 0.f};
                for (int j = lane; j < cnt; j += 32) {
                    #pragma unroll
                    for (int h = 0; h < NH; h++) {
                        float ex = expf(ssc[w][j][h] - mx[h]);
                        ssc[w][j][h] = ex;
                        sm[h] += ex;
                    }
                }
                #pragma unroll
                for (int h = 0; h < NH; h++) {
                    float s = wredsum(sm[h]);
                    if (lane == 0) sinv[w][h] = 1.f / s;
                }
            }
        }
        __syncthreads();
        {
            int slot = w >> 1;
            int p = grp * 4 + slot;
            if (p < nS) {
                int half = w & 1;
                int cnt = min(g_degS[p], MAXDEG);
                float inv[NH];
                #pragma unroll
                for (int h = 0; h < NH; h++) inv[h] = sinv[slot][h];
                int dbase = half * 256 + lane * 8;
                float4 a[NH][2];
                #pragma unroll
                for (int h = 0; h < NH; h++) { a[h][0] = make_float4(0, 0, 0, 0); a[h][1] = make_float4(0, 0, 0, 0); }
                for (int j = 0; j < cnt; j++) {
                    int s = ssrc[slot][j];
                    float wh[NH];
                    #pragma unroll
                    for (int h = 0; h < NH; h++) wh[h] = ssc[slot][j][h] * inv[h];
                    const float4* xp = reinterpret_cast<const float4*>(X + (size_t)s * FD + dbase);
                    float4 f0 = xp[0], f1 = xp[1];
                    #pragma unroll
                    for (int h = 0; h < NH; h++) {
                        a[h][0].x = fmaf(wh[h], f0.x, a[h][0].x); a[h][0].y = fmaf(wh[h], f0.y, a[h][0].y);
                        a[h][0].z = fmaf(wh[h], f0.z, a[h][0].z); a[h][0].w = fmaf(wh[h], f0.w, a[h][0].w);
                        a[h][1].x = fmaf(wh[h], f1.x, a[h][1].x); a[h][1].y = fmaf(wh[h], f1.y, a[h][1].y);
                        a[h][1].z = fmaf(wh[h], f1.z, a[h][1].z); a[h][1].w = fmaf(wh[h], f1.w, a[h][1].w);
                    }
                }
                #pragma unroll
                for (int h = 0; h < NH; h++) {
                    float* zp = g_z + ((size_t)p * NH + h) * FD + dbase;
                    *reinterpret_cast<float4*>(zp)     = a[h][0];
                    *reinterpret_cast<float4*>(zp + 4) = a[h][1];
                }
            }
        }
        __syncthreads();
    }
}

// ---------------- layer-1 head-blocked GEMM + fused el1/er1 epilogue ----------------
constexpr int BN = 128, BK = 16, GT = 256;

__global__ __launch_bounds__(GT) void k_gemm1(const float* __restrict__ W,
                                              const float* __restrict__ bias) {
    constexpr int RPT = 4, BM = 64, ALD = 4, WLD = 8;
    __shared__ __align__(16) float As[2][BK][BM + 4];
    __shared__ __align__(16) float Ws[2][BK][BN + 4];
    float* C = g_h1p;
    int nRows = min(g_nS, MAX_S);
    int nRT = (nRows + BM - 1) / BM;
    int nTiles = nRT * (FD / BN);
    int tid = threadIdx.x;
    int tr = tid >> 4, tc = tid & 15;
    int wc = tid & 127, wk0 = tid >> 7;
    int woff[WLD];
    #pragma unroll
    for (int i = 0; i < WLD; i++) woff[i] = (wk0 + i * 2) * FD + wc;

    for (int t = blockIdx.x; t < nTiles; t += gridDim.x) {
        int rt = t >> 2, ct = t & 3;              // ct == head
        int rbase = rt * BM, cbase = ct * BN;
        const float* aptr[ALD];
        #pragma unroll
        for (int i = 0; i < ALD; i++) {
            int gr = rbase + tr + i * 16;
            aptr[i] = (gr < nRows) ? (g_z + ((size_t)gr * NH + ct) * FD) : nullptr;
        }
        const float* wbase = W + cbase;

        unsigned long long acc[RPT][4];
        #pragma unroll
        for (int r = 0; r < RPT; r++)
            #pragma unroll
            for (int c = 0; c < 4; c++) acc[r][c] = 0ull;

        float aReg[ALD], wReg[WLD];
        #pragma unroll
        for (int i = 0; i < ALD; i++) aReg[i] = aptr[i] ? aptr[i][tc] : 0.f;
        #pragma unroll
        for (int i = 0; i < WLD; i++) wReg[i] = wbase[woff[i]];
        #pragma unroll
        for (int i = 0; i < ALD; i++) As[0][tc][tr + i * 16] = aReg[i];
        #pragma unroll
        for (int i = 0; i < WLD; i++) Ws[0][wk0 + i * 2][wc] = wReg[i];
        __syncthreads();

        int buf = 0;
        for (int kc = 0; kc < FD; kc += BK) {
            bool more = (kc + BK) < FD;
            if (more) {
                int kn = kc + BK;
                #pragma unroll
                for (int i = 0; i < ALD; i++) aReg[i] = aptr[i] ? aptr[i][kn + tc] : 0.f;
                #pragma unroll
                for (int i = 0; i < WLD; i++) wReg[i] = wbase[(size_t)kn * FD + woff[i]];
            }
            #pragma unroll
            for (int kk = 0; kk < BK; kk++) {
                float4 av = *reinterpret_cast<const float4*>(&As[buf][kk][tr * 4]);
                unsigned long long ad[4] = {dup2(av.x), dup2(av.y), dup2(av.z), dup2(av.w)};
                ulonglong2 b0 = *reinterpret_cast<const ulonglong2*>(&Ws[buf][kk][tc * 8]);
                ulonglong2 b1 = *reinterpret_cast<const ulonglong2*>(&Ws[buf][kk][tc * 8 + 4]);
                unsigned long long bp[4] = {b0.x, b0.y, b1.x, b1.y};
                #pragma unroll
                for (int r = 0; r < RPT; r++)
                    #pragma unroll
                    for (int c = 0; c < 4; c++)
                        fma2(acc[r][c], ad[r], bp[c]);
            }
            __syncthreads();
            if (more) {
                #pragma unroll
                for (int i = 0; i < ALD; i++) As[buf ^ 1][tc][tr + i * 16] = aReg[i];
                #pragma unroll
                for (int i = 0; i < WLD; i++) Ws[buf ^ 1][wk0 + i * 2][wc] = wReg[i];
            }
            __syncthreads();
            buf ^= 1;
        }

        const float4* b4 = reinterpret_cast<const float4*>(bias + cbase + tc * 8);
        float4 bb0 = b4[0], bb1 = b4[1];
        float4 wl[8], wr[8];
        #pragma unroll
        for (int i = 0; i < 8; i++) {
            wl[i] = g_wl1_4[cbase + tc * 8 + i];
            wr[i] = g_wr1_4[cbase + tc * 8 + i];
        }
        #pragma unroll
        for (int r = 0; r < RPT; r++) {
            int gr = rbase + tr * 4 + r;
            if (gr < nRows) {
                float2 p0 = unpack2(acc[r][0]);
                float2 p1 = unpack2(acc[r][1]);
                float2 p2 = unpack2(acc[r][2]);
                float2 p3 = unpack2(acc[r][3]);
                float vals[8] = {eluf(p0.x + bb0.x), eluf(p0.y + bb0.y),
                                 eluf(p1.x + bb0.z), eluf(p1.y + bb0.w),
                                 eluf(p2.x + bb1.x), eluf(p2.y + bb1.y),
                                 eluf(p3.x + bb1.z), eluf(p3.y + bb1.w)};
                float* cp = C + (size_t)gr * FD + cbase + tc * 8;
                *reinterpret_cast<float4*>(cp)     = make_float4(vals[0], vals[1], vals[2], vals[3]);
                *reinterpret_cast<float4*>(cp + 4) = make_float4(vals[4], vals[5], vals[6], vals[7]);
                float l0 = 0, l1 = 0, l2 = 0, l3 = 0, r0 = 0, r1 = 0, r2 = 0, r3 = 0;
                #pragma unroll
                for (int i = 0; i < 8; i++) {
                    l0 = fmaf(vals[i], wl[i].x, l0); l1 = fmaf(vals[i], wl[i].y, l1);
                    l2 = fmaf(vals[i], wl[i].z, l2); l3 = fmaf(vals[i], wl[i].w, l3);
                    r0 = fmaf(vals[i], wr[i].x, r0); r1 = fmaf(vals[i], wr[i].y, r1);
                    r2 = fmaf(vals[i], wr[i].z, r2); r3 = fmaf(vals[i], wr[i].w, r3);
                }
                float* elp = reinterpret_cast<float*>(&g_el1_4[gr]);
                float* erp = reinterpret_cast<float*>(&g_er1_4[gr]);
                atomicAdd(elp + 0, l0); atomicAdd(elp + 1, l1);
                atomicAdd(elp + 2, l2); atomicAdd(elp + 3, l3);
                atomicAdd(erp + 0, r0); atomicAdd(erp + 1, r1);
                atomicAdd(erp + 2, r2); atomicAdd(erp + 3, r3);
            }
        }
    }
}

// ---------------- layer-2 per-head aggregation (bucket-based: ids are in S) ----------------
__global__ __launch_bounds__(512) void k_agg2(const int* __restrict__ ids, int nIds) {
    __shared__ int   sps[16][MAXDEG];
    __shared__ float ssc[16][MAXDEG][NH];
    int wslot = threadIdx.x >> 5, lane = threadIdx.x & 31;
    int item = blockIdx.x * 16 + wslot;
    if (item >= nIds * 2) return;
    int i = item >> 1, half = item & 1;
    int v = ids[i];
    int pv = g_posS[v];
    int cnt = min(g_degS[pv], MAXDEG);

    float4 er4 = g_er1_4[pv];
    float erv[NH] = {er4.x, er4.y, er4.z, er4.w};
    float mx[NH] = {-1e30f, -1e30f, -1e30f, -1e30f};
    for (int j = lane; j < cnt; j += 32) {
        int s = g_bkt[(size_t)pv * MAXDEG + j];
        int ps = g_posS[s];
        sps[wslot][j] = ps;
        float4 el4 = g_el1_4[ps];
        float es[4] = {el4.x, el4.y, el4.z, el4.w};
        #pragma unroll
        for (int h = 0; h < NH; h++) {
            float x = es[h] + erv[h];
            x = (x > 0.f) ? x : 0.2f * x;
            ssc[wslot][j][h] = x;
            mx[h] = fmaxf(mx[h], x);
        }
    }
    #pragma unroll
    for (int h = 0; h < NH; h++) mx[h] = wredmax(mx[h]);
    __syncwarp();
    float sm[NH] = {0.f, 0.f, 0.f, 0.f};
    for (int j = lane; j < cnt; j += 32) {
        #pragma unroll
        for (int h = 0; h < NH; h++) {
            float ex = expf(ssc[wslot][j][h] - mx[h]);
            ssc[wslot][j][h] = ex;
            sm[h] += ex;
        }
    }
    float inv[NH];
    #pragma unroll
    for (int h = 0; h < NH; h++) inv[h] = 1.f / wredsum(sm[h]);
    __syncwarp();

    int dbase = half * 256 + lane * 8;
    float4 a[NH][2];
    #pragma unroll
    for (int h = 0; h < NH; h++) { a[h][0] = make_float4(0, 0, 0, 0); a[h][1] = make_float4(0, 0, 0, 0); }
    for (int j = 0; j < cnt; j++) {
        int ps = sps[wslot][j];
        float wh[NH];
        #pragma unroll
        for (int h = 0; h < NH; h++) wh[h] = ssc[wslot][j][h] * inv[h];
        const float4* fp = reinterpret_cast<const float4*>(g_h1p + (size_t)ps * FD + dbase);
        float4 f0 = fp[0], f1 = fp[1];
        #pragma unroll
        for (int h = 0; h < NH; h++) {
            a[h][0].x = fmaf(wh[h], f0.x, a[h][0].x); a[h][0].y = fmaf(wh[h], f0.y, a[h][0].y);
            a[h][0].z = fmaf(wh[h], f0.z, a[h][0].z); a[h][0].w = fmaf(wh[h], f0.w, a[h][0].w);
            a[h][1].x = fmaf(wh[h], f1.x, a[h][1].x); a[h][1].y = fmaf(wh[h], f1.y, a[h][1].y);
            a[h][1].z = fmaf(wh[h], f1.z, a[h][1].z); a[h][1].w = fmaf(wh[h], f1.w, a[h][1].w);
        }
    }
    #pragma unroll
    for (int h = 0; h < NH; h++) {
        float* zp = g_z2 + ((size_t)i * NH + h) * FD + dbase;
        *reinterpret_cast<float4*>(zp)     = a[h][0];
        *reinterpret_cast<float4*>(zp + 4) = a[h][1];
    }
}

// ---------------- final ----------------
__global__ __launch_bounds__(256) void k_final(const float* __restrict__ W1,
                                               const float* __restrict__ bias1,
                                               const int* __restrict__ ids, int nIds,
                                               float* __restrict__ out) {
    int c = blockIdx.x * 32 + (threadIdx.x & 31);
    int hc = c >> 7;
    int rg = threadIdx.x >> 5;
    const float* wc = W1 + c;
    const float* z0 = g_z2 + ((size_t)rg * NH + hc) * FD;
    const float* z1 = g_z2 + ((size_t)(rg + 8) * NH + hc) * FD;
    float acc0 = 0.f, acc1 = 0.f;
    for (int k = 0; k < FD; k += 4) {
        float4 a = *reinterpret_cast<const float4*>(z0 + k);
        float4 b = *reinterpret_cast<const float4*>(z1 + k);
        float w0 = wc[(size_t)(k + 0) * FD];
        float w1 = wc[(size_t)(k + 1) * FD];
        float w2 = wc[(size_t)(k + 2) * FD];
        float w3 = wc[(size_t)(k + 3) * FD];
        acc0 = fmaf(a.x, w0, acc0); acc0 = fmaf(a.y, w1, acc0);
        acc0 = fmaf(a.z, w2, acc0); acc0 = fmaf(a.w, w3, acc0);
        acc1 = fmaf(b.x, w0, acc1); acc1 = fmaf(b.y, w1, acc1);
        acc1 = fmaf(b.z, w2, acc1); acc1 = fmaf(b.w, w3, acc1);
    }
    float bv = bias1[c];
    if (rg < nIds) {
        int pv = g_posS[ids[rg]];
        float x = acc0 + g_h1p[(size_t)pv * FD + c] + bv;
        out[(size_t)rg * FD + c] = tanhf(eluf(x));
    }
    int r2 = rg + 8;
    if (r2 < nIds) {
        int pv = g_posS[ids[r2]];
        float x = acc1 + g_h1p[(size_t)pv * FD + c] + bv;
        out[(size_t)r2 * FD + c] = tanhf(eluf(x));
    }
}

// ---------------- launch ----------------
extern "C" void kernel_launch(void* const* d_in, const int* in_sizes, int n_in,
                              void* d_out, int out_size) {
    const float* features = (const float*)d_in[0];
    const float* fc_w0    = (const float*)d_in[1];
    const float* attn_l0  = (const float*)d_in[2];
    const float* attn_r0  = (const float*)d_in[3];
    const float* bias0    = (const float*)d_in[4];
    const float* fc_w1    = (const float*)d_in[5];
    const float* attn_l1  = (const float*)d_in[6];
    const float* attn_r1  = (const float*)d_in[7];
    const float* bias1    = (const float*)d_in[8];
    const int*   src      = (const int*)d_in[9];
    const int*   dst      = (const int*)d_in[10];
    const int*   ids      = (const int*)d_in[11];
    int E    = in_sizes[9];
    int nIds = in_sizes[11];
    float* out = (float*)d_out;

    k_setup<<<128, 256>>>(fc_w0, attn_l0, attn_r0, fc_w1, attn_l1, attn_r1);
    k_scan_e2<<<1184, 256>>>(src, dst, ids, nIds, E);
    k_scan_e1<<<1184, 256>>>(src, dst, E);

    // layer 1
    k_eler0<<<592, 256>>>(features);
    k_agg1<<<296, 256>>>(features);
    k_gemm1<<<36, GT>>>(fc_w0, bias0);

    // layer 2
    k_agg2<<<2, 512>>>(ids, nIds);
    k_final<<<16, 256>>>(fc_w1, bias1, ids, nIds, out);
}

// round 17
// speedup vs baseline: 1.2290x; 1.0372x over previous
#include <cuda_runtime.h>
#include <math.h>

#define NN 50000
#define FD 512
#define NH 4

constexpr int MAX_S  = 8192;
constexpr int MAX_U  = 262144;
constexpr int MAXDEG = 128;
constexpr int MAXIDS = 32;
constexpr int NMSK   = 1600;   // ceil(50000/32)

// ---------------- static device scratch ----------------
__device__ float4 g_el4[NN];
__device__ float4 g_er4[NN];
__device__ float  g_z[(size_t)MAX_S * NH * FD];
__device__ float  g_h1p[(size_t)MAX_S * FD];
__device__ float4 g_el1_4[MAX_S];
__device__ float4 g_er1_4[MAX_S];
__device__ float  g_z2[(size_t)MAXIDS * NH * FD];
__device__ float4 g_wl0_4[FD], g_wr0_4[FD], g_wl1_4[FD], g_wr1_4[FD];
__device__ float  g_wl0T[NH * FD], g_wr0T[NH * FD];   // transposed: [h][k]
__device__ unsigned g_mskS[NMSK], g_mskU[NMSK];
__device__ int g_S[MAX_S], g_posS[NN], g_degS[MAX_S];
__device__ int g_bkt[(size_t)MAX_S * MAXDEG];
__device__ int g_U[MAX_U];
__device__ int g_nS, g_nU;

// ---------------- helpers ----------------
__device__ __forceinline__ unsigned long long dup2(float a) {
    unsigned long long r;
    unsigned int ai = __float_as_uint(a);
    asm("mov.b64 %0, {%1, %1};" : "=l"(r) : "r"(ai));
    return r;
}
__device__ __forceinline__ void fma2(unsigned long long& d, unsigned long long a, unsigned long long b) {
    asm("fma.rn.f32x2 %0, %1, %2, %0;" : "+l"(d) : "l"(a), "l"(b));
}
__device__ __forceinline__ float2 unpack2(unsigned long long v) {
    float2 r;
    r.x = __uint_as_float((unsigned int)(v & 0xffffffffull));
    r.y = __uint_as_float((unsigned int)(v >> 32));
    return r;
}
__device__ __forceinline__ float wredsum(float x) {
    #pragma unroll
    for (int o = 16; o > 0; o >>= 1) x += __shfl_xor_sync(0xffffffffu, x, o);
    return x;
}
__device__ __forceinline__ float wredmax(float x) {
    #pragma unroll
    for (int o = 16; o > 0; o >>= 1) x = fmaxf(x, __shfl_xor_sync(0xffffffffu, x, o));
    return x;
}
__device__ __forceinline__ float eluf(float x) { return (x > 0.f) ? x : expm1f(x); }

// ---------------- setup: zero scratch + projected attention vectors (plain + transposed) ----------------
__global__ __launch_bounds__(256) void k_setup(const float* __restrict__ W0,
                                               const float* __restrict__ al0, const float* __restrict__ ar0,
                                               const float* __restrict__ W1,
                                               const float* __restrict__ al1, const float* __restrict__ ar1) {
    int gi = blockIdx.x * 256 + threadIdx.x;
    if (gi < MAX_S) {
        g_degS[gi] = 0;
        g_el1_4[gi] = make_float4(0, 0, 0, 0);
        g_er1_4[gi] = make_float4(0, 0, 0, 0);
    }
    if (gi < NMSK) { g_mskS[gi] = 0; g_mskU[gi] = 0; }
    if (gi == 0) { g_nS = 0; g_nU = 0; }

    int lane = threadIdx.x & 31;
    int w = gi >> 5;
    if (w >= FD) return;
    const float4* w0r = reinterpret_cast<const float4*>(W0 + (size_t)w * FD);
    const float4* w1r = reinterpret_cast<const float4*>(W1 + (size_t)w * FD);
    const float4* l0 = reinterpret_cast<const float4*>(al0);
    const float4* r0 = reinterpret_cast<const float4*>(ar0);
    const float4* l1 = reinterpret_cast<const float4*>(al1);
    const float4* r1 = reinterpret_cast<const float4*>(ar1);
    float sl0[NH], sr0[NH], sl1[NH], sr1[NH];
    #pragma unroll
    for (int h = 0; h < NH; h++) {
        float4 a0 = w0r[h * 32 + lane];
        float4 b0l = l0[h * 32 + lane];
        float4 b0r = r0[h * 32 + lane];
        sl0[h] = wredsum(a0.x * b0l.x + a0.y * b0l.y + a0.z * b0l.z + a0.w * b0l.w);
        sr0[h] = wredsum(a0.x * b0r.x + a0.y * b0r.y + a0.z * b0r.z + a0.w * b0r.w);
        float4 a1 = w1r[h * 32 + lane];
        float4 b1l = l1[h * 32 + lane];
        float4 b1r = r1[h * 32 + lane];
        sl1[h] = wredsum(a1.x * b1l.x + a1.y * b1l.y + a1.z * b1l.z + a1.w * b1l.w);
        sr1[h] = wredsum(a1.x * b1r.x + a1.y * b1r.y + a1.z * b1r.z + a1.w * b1r.w);
    }
    if (lane == 0) {
        g_wl0_4[w] = make_float4(sl0[0], sl0[1], sl0[2], sl0[3]);
        g_wr0_4[w] = make_float4(sr0[0], sr0[1], sr0[2], sr0[3]);
        g_wl1_4[w] = make_float4(sl1[0], sl1[1], sl1[2], sl1[3]);
        g_wr1_4[w] = make_float4(sr1[0], sr1[1], sr1[2], sr1[3]);
        #pragma unroll
        for (int h = 0; h < NH; h++) {
            g_wl0T[h * FD + w] = sl0[h];
            g_wr0T[h * FD + w] = sr0[h];
        }
    }
}

// ---------------- scan e2: edges into ids -> build S (smem id-bitmask) ----------------
__global__ __launch_bounds__(256) void k_scan_e2(const int* __restrict__ src, const int* __restrict__ dst,
                                                 const int* __restrict__ ids, int nIds, int E) {
    __shared__ unsigned smsk[NMSK];
    for (int i = threadIdx.x; i < NMSK; i += 256) smsk[i] = 0;
    __syncthreads();
    if (threadIdx.x < nIds) {
        int v = ids[threadIdx.x];
        atomicOr(&smsk[v >> 5], 1u << (v & 31));
    }
    __syncthreads();
    int i = blockIdx.x * blockDim.x + threadIdx.x;
    int stride = gridDim.x * blockDim.x;
    int E4 = E >> 2;
    const int4* d4 = reinterpret_cast<const int4*>(dst);
    auto proc = [&](int dd, int e) {
        if ((smsk[dd >> 5] >> (dd & 31)) & 1u) {
            int s = src[e];
            unsigned m = 1u << (s & 31);
            unsigned old = atomicOr(&g_mskS[s >> 5], m);
            if (!(old & m)) {
                int p = atomicAdd(&g_nS, 1);
                if (p < MAX_S) { g_S[p] = s; g_posS[s] = p; }
            }
        }
    };
    for (int q = i; q < E4; q += stride) {
        int4 d = d4[q];
        int e = q * 4;
        proc(d.x, e); proc(d.y, e + 1); proc(d.z, e + 2); proc(d.w, e + 3);
    }
    for (int e = E4 * 4 + i; e < E; e += stride) proc(dst[e], e);
}

// ---------------- scan e1: bucket edges into S (smem S-bitmask); build U ----------------
__global__ __launch_bounds__(256) void k_scan_e1(const int* __restrict__ src, const int* __restrict__ dst, int E) {
    __shared__ unsigned smsk[NMSK];
    for (int i = threadIdx.x; i < NMSK; i += 256) smsk[i] = g_mskS[i];
    __syncthreads();
    int i = blockIdx.x * blockDim.x + threadIdx.x;
    int stride = gridDim.x * blockDim.x;
    int E4 = E >> 2;
    const int4* d4 = reinterpret_cast<const int4*>(dst);
    auto proc = [&](int dd, int e) {
        if ((smsk[dd >> 5] >> (dd & 31)) & 1u) {
            int p = g_posS[dd];
            int s = src[e];
            int slot = atomicAdd(&g_degS[p], 1);
            if (slot < MAXDEG) g_bkt[(size_t)p * MAXDEG + slot] = s;
            unsigned m = 1u << (s & 31);
            if (!((g_mskU[s >> 5] >> (s & 31)) & 1u)) {
                unsigned old = atomicOr(&g_mskU[s >> 5], m);
                if (!(old & m)) {
                    int u = atomicAdd(&g_nU, 1);
                    if (u < MAX_U) g_U[u] = s;
                }
            }
        }
    };
    for (int q = i; q < E4; q += stride) {
        int4 d = d4[q];
        int e = q * 4;
        proc(d.x, e); proc(d.y, e + 1); proc(d.z, e + 2); proc(d.w, e + 3);
    }
    for (int e = E4 * 4 + i; e < E; e += stride) proc(dst[e], e);
}

// ---------------- el over U (4 nodes/warp-iter), er over S — conflict-free transposed tables ----------------
__global__ __launch_bounds__(256) void k_eler0(const float* __restrict__ X) {
    __shared__ float swlT[NH * FD];   // 8KB, [h][k]
    __shared__ float swrT[NH * FD];   // 8KB
    for (int k = threadIdx.x; k < NH * FD; k += 256) { swlT[k] = g_wl0T[k]; swrT[k] = g_wr0T[k]; }
    __syncthreads();
    int lane = threadIdx.x & 31;
    int w = (blockIdx.x * blockDim.x + threadIdx.x) >> 5;
    int nw = (gridDim.x * blockDim.x) >> 5;
    int n = min(g_nU, MAX_U);
    for (int g = w * 4; g < n; g += nw * 4) {
        int v0 = g_U[g];
        int v1 = (g + 1 < n) ? g_U[g + 1] : v0;
        int v2 = (g + 2 < n) ? g_U[g + 2] : v0;
        int v3 = (g + 3 < n) ? g_U[g + 3] : v0;
        const float4* x0 = reinterpret_cast<const float4*>(X + (size_t)v0 * FD);
        const float4* x1 = reinterpret_cast<const float4*>(X + (size_t)v1 * FD);
        const float4* x2 = reinterpret_cast<const float4*>(X + (size_t)v2 * FD);
        const float4* x3 = reinterpret_cast<const float4*>(X + (size_t)v3 * FD);
        float a0[NH] = {0, 0, 0, 0}, a1[NH] = {0, 0, 0, 0};
        float a2[NH] = {0, 0, 0, 0}, a3[NH] = {0, 0, 0, 0};
        #pragma unroll
        for (int i = 0; i < 4; i++) {
            float4 p0 = x0[i * 32 + lane];
            float4 p1 = x1[i * 32 + lane];
            float4 p2 = x2[i * 32 + lane];
            float4 p3 = x3[i * 32 + lane];
            int kb = (i * 32 + lane) * 4;
            #pragma unroll
            for (int h = 0; h < NH; h++) {
                float4 w4 = *reinterpret_cast<const float4*>(&swlT[h * FD + kb]);
                a0[h] += p0.x * w4.x + p0.y * w4.y + p0.z * w4.z + p0.w * w4.w;
                a1[h] += p1.x * w4.x + p1.y * w4.y + p1.z * w4.z + p1.w * w4.w;
                a2[h] += p2.x * w4.x + p2.y * w4.y + p2.z * w4.z + p2.w * w4.w;
                a3[h] += p3.x * w4.x + p3.y * w4.y + p3.z * w4.z + p3.w * w4.w;
            }
        }
        #pragma unroll
        for (int h = 0; h < NH; h++) {
            a0[h] = wredsum(a0[h]); a1[h] = wredsum(a1[h]);
            a2[h] = wredsum(a2[h]); a3[h] = wredsum(a3[h]);
        }
        if (lane == 0) {
            g_el4[v0] = make_float4(a0[0], a0[1], a0[2], a0[3]);
            if (g + 1 < n) g_el4[v1] = make_float4(a1[0], a1[1], a1[2], a1[3]);
            if (g + 2 < n) g_el4[v2] = make_float4(a2[0], a2[1], a2[2], a2[3]);
            if (g + 3 < n) g_el4[v3] = make_float4(a3[0], a3[1], a3[2], a3[3]);
        }
    }
    // er pass: only S nodes need er (they are the dsts)
    int nS = min(g_nS, MAX_S);
    for (int g = w; g < nS; g += nw) {
        int v = g_S[g];
        const float4* xr = reinterpret_cast<const float4*>(X + (size_t)v * FD);
        float aR[NH] = {0, 0, 0, 0};
        #pragma unroll
        for (int i = 0; i < 4; i++) {
            float4 x4 = xr[i * 32 + lane];
            int kb = (i * 32 + lane) * 4;
            #pragma unroll
            for (int h = 0; h < NH; h++) {
                float4 w4 = *reinterpret_cast<const float4*>(&swrT[h * FD + kb]);
                aR[h] += x4.x * w4.x + x4.y * w4.y + x4.z * w4.z + x4.w * w4.w;
            }
        }
        #pragma unroll
        for (int h = 0; h < NH; h++) aR[h] = wredsum(aR[h]);
        if (lane == 0) g_er4[v] = make_float4(aR[0], aR[1], aR[2], aR[3]);
    }
}

// ---------------- layer-1 per-head aggregation; block = 4 dsts, scores shared ----------------
__global__ __launch_bounds__(256) void k_agg1(const float* __restrict__ X) {
    __shared__ int   ssrc[4][MAXDEG];
    __shared__ float ssc[4][MAXDEG][NH];
    __shared__ float sinv[4][NH];
    int w = threadIdx.x >> 5, lane = threadIdx.x & 31;
    int nS = min(g_nS, MAX_S);
    int nGrp = (nS + 3) >> 2;
    for (int grp = blockIdx.x; grp < nGrp; grp += gridDim.x) {
        if (w < 4) {
            int p = grp * 4 + w;
            if (p < nS) {
                int v = g_S[p];
                int cnt = min(g_degS[p], MAXDEG);
                float4 er4 = g_er4[v];
                float erv[NH] = {er4.x, er4.y, er4.z, er4.w};
                float mx[NH] = {-1e30f, -1e30f, -1e30f, -1e30f};
                for (int j = lane; j < cnt; j += 32) {
                    int s = g_bkt[(size_t)p * MAXDEG + j];
                    ssrc[w][j] = s;
                    float4 el4 = g_el4[s];
                    float es[4] = {el4.x, el4.y, el4.z, el4.w};
                    #pragma unroll
                    for (int h = 0; h < NH; h++) {
                        float x = es[h] + erv[h];
                        x = (x > 0.f) ? x : 0.2f * x;
                        ssc[w][j][h] = x;
                        mx[h] = fmaxf(mx[h], x);
                    }
                }
                #pragma unroll
                for (int h = 0; h < NH; h++) mx[h] = wredmax(mx[h]);
                __syncwarp();
                float sm[NH] = {0.f, 0.f, 0.f, 0.f};
                for (int j = lane; j < cnt; j += 32) {
                    #pragma unroll
                    for (int h = 0; h < NH; h++) {
                        float ex = expf(ssc[w][j][h] - mx[h]);
                        ssc[w][j][h] = ex;
                        sm[h] += ex;
                    }
                }
                #pragma unroll
                for (int h = 0; h < NH; h++) {
                    float s = wredsum(sm[h]);
                    if (lane == 0) sinv[w][h] = 1.f / s;
                }
            }
        }
        __syncthreads();
        {
            int slot = w >> 1;
            int p = grp * 4 + slot;
            if (p < nS) {
                int half = w & 1;
                int cnt = min(g_degS[p], MAXDEG);
                float inv[NH];
                #pragma unroll
                for (int h = 0; h < NH; h++) inv[h] = sinv[slot][h];
                int dbase = half * 256 + lane * 8;
                float4 a[NH][2];
                #pragma unroll
                for (int h = 0; h < NH; h++) { a[h][0] = make_float4(0, 0, 0, 0); a[h][1] = make_float4(0, 0, 0, 0); }
                int j = 0;
                for (; j + 2 <= cnt; j += 2) {
                    int s0 = ssrc[slot][j];
                    int s1 = ssrc[slot][j + 1];
                    float wh0[NH], wh1[NH];
                    #pragma unroll
                    for (int h = 0; h < NH; h++) {
                        wh0[h] = ssc[slot][j][h] * inv[h];
                        wh1[h] = ssc[slot][j + 1][h] * inv[h];
                    }
                    const float4* xp0 = reinterpret_cast<const float4*>(X + (size_t)s0 * FD + dbase);
                    const float4* xp1 = reinterpret_cast<const float4*>(X + (size_t)s1 * FD + dbase);
                    float4 f00 = xp0[0], f01 = xp0[1];
                    float4 f10 = xp1[0], f11 = xp1[1];
                    #pragma unroll
                    for (int h = 0; h < NH; h++) {
                        a[h][0].x = fmaf(wh0[h], f00.x, a[h][0].x); a[h][0].y = fmaf(wh0[h], f00.y, a[h][0].y);
                        a[h][0].z = fmaf(wh0[h], f00.z, a[h][0].z); a[h][0].w = fmaf(wh0[h], f00.w, a[h][0].w);
                        a[h][1].x = fmaf(wh0[h], f01.x, a[h][1].x); a[h][1].y = fmaf(wh0[h], f01.y, a[h][1].y);
                        a[h][1].z = fmaf(wh0[h], f01.z, a[h][1].z); a[h][1].w = fmaf(wh0[h], f01.w, a[h][1].w);
                        a[h][0].x = fmaf(wh1[h], f10.x, a[h][0].x); a[h][0].y = fmaf(wh1[h], f10.y, a[h][0].y);
                        a[h][0].z = fmaf(wh1[h], f10.z, a[h][0].z); a[h][0].w = fmaf(wh1[h], f10.w, a[h][0].w);
                        a[h][1].x = fmaf(wh1[h], f11.x, a[h][1].x); a[h][1].y = fmaf(wh1[h], f11.y, a[h][1].y);
                        a[h][1].z = fmaf(wh1[h], f11.z, a[h][1].z); a[h][1].w = fmaf(wh1[h], f11.w, a[h][1].w);
                    }
                }
                for (; j < cnt; j++) {
                    int s = ssrc[slot][j];
                    float wh[NH];
                    #pragma unroll
                    for (int h = 0; h < NH; h++) wh[h] = ssc[slot][j][h] * inv[h];
                    const float4* xp = reinterpret_cast<const float4*>(X + (size_t)s * FD + dbase);
                    float4 f0 = xp[0], f1 = xp[1];
                    #pragma unroll
                    for (int h = 0; h < NH; h++) {
                        a[h][0].x = fmaf(wh[h], f0.x, a[h][0].x); a[h][0].y = fmaf(wh[h], f0.y, a[h][0].y);
                        a[h][0].z = fmaf(wh[h], f0.z, a[h][0].z); a[h][0].w = fmaf(wh[h], f0.w, a[h][0].w);
                        a[h][1].x = fmaf(wh[h], f1.x, a[h][1].x); a[h][1].y = fmaf(wh[h], f1.y, a[h][1].y);
                        a[h][1].z = fmaf(wh[h], f1.z, a[h][1].z); a[h][1].w = fmaf(wh[h], f1.w, a[h][1].w);
                    }
                }
                #pragma unroll
                for (int h = 0; h < NH; h++) {
                    float* zp = g_z + ((size_t)p * NH + h) * FD + dbase;
                    *reinterpret_cast<float4*>(zp)     = a[h][0];
                    *reinterpret_cast<float4*>(zp + 4) = a[h][1];
                }
            }
        }
        __syncthreads();
    }
}

// ---------------- layer-1 head-blocked GEMM + fused el1/er1 epilogue ----------------
constexpr int BN = 128, BK = 16, GT = 256;

__global__ __launch_bounds__(GT) void k_gemm1(const float* __restrict__ W,
                                              const float* __restrict__ bias) {
    constexpr int RPT = 4, BM = 64, ALD = 4, WLD = 8;
    __shared__ __align__(16) float As[2][BK][BM + 4];
    __shared__ __align__(16) float Ws[2][BK][BN + 4];
    float* C = g_h1p;
    int nRows = min(g_nS, MAX_S);
    int nRT = (nRows + BM - 1) / BM;
    int nTiles = nRT * (FD / BN);
    int tid = threadIdx.x;
    int tr = tid >> 4, tc = tid & 15;
    int wc = tid & 127, wk0 = tid >> 7;
    int woff[WLD];
    #pragma unroll
    for (int i = 0; i < WLD; i++) woff[i] = (wk0 + i * 2) * FD + wc;

    for (int t = blockIdx.x; t < nTiles; t += gridDim.x) {
        int rt = t >> 2, ct = t & 3;              // ct == head
        int rbase = rt * BM, cbase = ct * BN;
        const float* aptr[ALD];
        #pragma unroll
        for (int i = 0; i < ALD; i++) {
            int gr = rbase + tr + i * 16;
            aptr[i] = (gr < nRows) ? (g_z + ((size_t)gr * NH + ct) * FD) : nullptr;
        }
        const float* wbase = W + cbase;

        unsigned long long acc[RPT][4];
        #pragma unroll
        for (int r = 0; r < RPT; r++)
            #pragma unroll
            for (int c = 0; c < 4; c++) acc[r][c] = 0ull;

        float aReg[ALD], wReg[WLD];
        #pragma unroll
        for (int i = 0; i < ALD; i++) aReg[i] = aptr[i] ? aptr[i][tc] : 0.f;
        #pragma unroll
        for (int i = 0; i < WLD; i++) wReg[i] = wbase[woff[i]];
        #pragma unroll
        for (int i = 0; i < ALD; i++) As[0][tc][tr + i * 16] = aReg[i];
        #pragma unroll
        for (int i = 0; i < WLD; i++) Ws[0][wk0 + i * 2][wc] = wReg[i];
        __syncthreads();

        int buf = 0;
        for (int kc = 0; kc < FD; kc += BK) {
            bool more = (kc + BK) < FD;
            if (more) {
                int kn = kc + BK;
                #pragma unroll
                for (int i = 0; i < ALD; i++) aReg[i] = aptr[i] ? aptr[i][kn + tc] : 0.f;
                #pragma unroll
                for (int i = 0; i < WLD; i++) wReg[i] = wbase[(size_t)kn * FD + woff[i]];
            }
            #pragma unroll
            for (int kk = 0; kk < BK; kk++) {
                float4 av = *reinterpret_cast<const float4*>(&As[buf][kk][tr * 4]);
                unsigned long long ad[4] = {dup2(av.x), dup2(av.y), dup2(av.z), dup2(av.w)};
                ulonglong2 b0 = *reinterpret_cast<const ulonglong2*>(&Ws[buf][kk][tc * 8]);
                ulonglong2 b1 = *reinterpret_cast<const ulonglong2*>(&Ws[buf][kk][tc * 8 + 4]);
                unsigned long long bp[4] = {b0.x, b0.y, b1.x, b1.y};
                #pragma unroll
                for (int r = 0; r < RPT; r++)
                    #pragma unroll
                    for (int c = 0; c < 4; c++)
                        fma2(acc[r][c], ad[r], bp[c]);
            }
            __syncthreads();
            if (more) {
                #pragma unroll
                for (int i = 0; i < ALD; i++) As[buf ^ 1][tc][tr + i * 16] = aReg[i];
                #pragma unroll
                for (int i = 0; i < WLD; i++) Ws[buf ^ 1][wk0 + i * 2][wc] = wReg[i];
            }
            __syncthreads();
            buf ^= 1;
        }

        const float4* b4 = reinterpret_cast<const float4*>(bias + cbase + tc * 8);
        float4 bb0 = b4[0], bb1 = b4[1];
        float4 wl[8], wr[8];
        #pragma unroll
        for (int i = 0; i < 8; i++) {
            wl[i] = g_wl1_4[cbase + tc * 8 + i];
            wr[i] = g_wr1_4[cbase + tc * 8 + i];
        }
        #pragma unroll
        for (int r = 0; r < RPT; r++) {
            int gr = rbase + tr * 4 + r;
            if (gr < nRows) {
                float2 p0 = unpack2(acc[r][0]);
                float2 p1 = unpack2(acc[r][1]);
                float2 p2 = unpack2(acc[r][2]);
                float2 p3 = unpack2(acc[r][3]);
                float vals[8] = {eluf(p0.x + bb0.x), eluf(p0.y + bb0.y),
                                 eluf(p1.x + bb0.z), eluf(p1.y + bb0.w),
                                 eluf(p2.x + bb1.x), eluf(p2.y + bb1.y),
                                 eluf(p3.x + bb1.z), eluf(p3.y + bb1.w)};
                float* cp = C + (size_t)gr * FD + cbase + tc * 8;
                *reinterpret_cast<float4*>(cp)     = make_float4(vals[0], vals[1], vals[2], vals[3]);
                *reinterpret_cast<float4*>(cp + 4) = make_float4(vals[4], vals[5], vals[6], vals[7]);
                float l0 = 0, l1 = 0, l2 = 0, l3 = 0, r0 = 0, r1 = 0, r2 = 0, r3 = 0;
                #pragma unroll
                for (int i = 0; i < 8; i++) {
                    l0 = fmaf(vals[i], wl[i].x, l0); l1 = fmaf(vals[i], wl[i].y, l1);
                    l2 = fmaf(vals[i], wl[i].z, l2); l3 = fmaf(vals[i], wl[i].w, l3);
                    r0 = fmaf(vals[i], wr[i].x, r0); r1 = fmaf(vals[i], wr[i].y, r1);
                    r2 = fmaf(vals[i], wr[i].z, r2); r3 = fmaf(vals[i], wr[i].w, r3);
                }
                float* elp = reinterpret_cast<float*>(&g_el1_4[gr]);
                float* erp = reinterpret_cast<float*>(&g_er1_4[gr]);
                atomicAdd(elp + 0, l0); atomicAdd(elp + 1, l1);
                atomicAdd(elp + 2, l2); atomicAdd(elp + 3, l3);
                atomicAdd(erp + 0, r0); atomicAdd(erp + 1, r1);
                atomicAdd(erp + 2, r2); atomicAdd(erp + 3, r3);
            }
        }
    }
}

// ---------------- layer-2 per-head aggregation (bucket-based: ids are in S) ----------------
__global__ __launch_bounds__(512) void k_agg2(const int* __restrict__ ids, int nIds) {
    __shared__ int   sps[16][MAXDEG];
    __shared__ float ssc[16][MAXDEG][NH];
    int wslot = threadIdx.x >> 5, lane = threadIdx.x & 31;
    int item = blockIdx.x * 16 + wslot;
    if (item >= nIds * 2) return;
    int i = item >> 1, half = item & 1;
    int v = ids[i];
    int pv = g_posS[v];
    int cnt = min(g_degS[pv], MAXDEG);

    float4 er4 = g_er1_4[pv];
    float erv[NH] = {er4.x, er4.y, er4.z, er4.w};
    float mx[NH] = {-1e30f, -1e30f, -1e30f, -1e30f};
    for (int j = lane; j < cnt; j += 32) {
        int s = g_bkt[(size_t)pv * MAXDEG + j];
        int ps = g_posS[s];
        sps[wslot][j] = ps;
        float4 el4 = g_el1_4[ps];
        float es[4] = {el4.x, el4.y, el4.z, el4.w};
        #pragma unroll
        for (int h = 0; h < NH; h++) {
            float x = es[h] + erv[h];
            x = (x > 0.f) ? x : 0.2f * x;
            ssc[wslot][j][h] = x;
            mx[h] = fmaxf(mx[h], x);
        }
    }
    #pragma unroll
    for (int h = 0; h < NH; h++) mx[h] = wredmax(mx[h]);
    __syncwarp();
    float sm[NH] = {0.f, 0.f, 0.f, 0.f};
    for (int j = lane; j < cnt; j += 32) {
        #pragma unroll
        for (int h = 0; h < NH; h++) {
            float ex = expf(ssc[wslot][j][h] - mx[h]);
            ssc[wslot][j][h] = ex;
            sm[h] += ex;
        }
    }
    float inv[NH];
    #pragma unroll
    for (int h = 0; h < NH; h++) inv[h] = 1.f / wredsum(sm[h]);
    __syncwarp();

    int dbase = half * 256 + lane * 8;
    float4 a[NH][2];
    #pragma unroll
    for (int h = 0; h < NH; h++) { a[h][0] = make_float4(0, 0, 0, 0); a[h][1] = make_float4(0, 0, 0, 0); }
    for (int j = 0; j < cnt; j++) {
        int ps = sps[wslot][j];
        float wh[NH];
        #pragma unroll
        for (int h = 0; h < NH; h++) wh[h] = ssc[wslot][j][h] * inv[h];
        const float4* fp = reinterpret_cast<const float4*>(g_h1p + (size_t)ps * FD + dbase);
        float4 f0 = fp[0], f1 = fp[1];
        #pragma unroll
        for (int h = 0; h < NH; h++) {
            a[h][0].x = fmaf(wh[h], f0.x, a[h][0].x); a[h][0].y = fmaf(wh[h], f0.y, a[h][0].y);
            a[h][0].z = fmaf(wh[h], f0.z, a[h][0].z); a[h][0].w = fmaf(wh[h], f0.w, a[h][0].w);
            a[h][1].x = fmaf(wh[h], f1.x, a[h][1].x); a[h][1].y = fmaf(wh[h], f1.y, a[h][1].y);
            a[h][1].z = fmaf(wh[h], f1.z, a[h][1].z); a[h][1].w = fmaf(wh[h], f1.w, a[h][1].w);
        }
    }
    #pragma unroll
    for (int h = 0; h < NH; h++) {
        float* zp = g_z2 + ((size_t)i * NH + h) * FD + dbase;
        *reinterpret_cast<float4*>(zp)     = a[h][0];
        *reinterpret_cast<float4*>(zp + 4) = a[h][1];
    }
}

// ---------------- final ----------------
__global__ __launch_bounds__(256) void k_final(const float* __restrict__ W1,
                                               const float* __restrict__ bias1,
                                               const int* __restrict__ ids, int nIds,
                                               float* __restrict__ out) {
    int c = blockIdx.x * 32 + (threadIdx.x & 31);
    int hc = c >> 7;
    int rg = threadIdx.x >> 5;
    const float* wc = W1 + c;
    const float* z0 = g_z2 + ((size_t)rg * NH + hc) * FD;
    const float* z1 = g_z2 + ((size_t)(rg + 8) * NH + hc) * FD;
    float acc0 = 0.f, acc1 = 0.f;
    for (int k = 0; k < FD; k += 4) {
        float4 a = *reinterpret_cast<const float4*>(z0 + k);
        float4 b = *reinterpret_cast<const float4*>(z1 + k);
        float w0 = wc[(size_t)(k + 0) * FD];
        float w1 = wc[(size_t)(k + 1) * FD];
        float w2 = wc[(size_t)(k + 2) * FD];
        float w3 = wc[(size_t)(k + 3) * FD];
        acc0 = fmaf(a.x, w0, acc0); acc0 = fmaf(a.y, w1, acc0);
        acc0 = fmaf(a.z, w2, acc0); acc0 = fmaf(a.w, w3, acc0);
        acc1 = fmaf(b.x, w0, acc1); acc1 = fmaf(b.y, w1, acc1);
        acc1 = fmaf(b.z, w2, acc1); acc1 = fmaf(b.w, w3, acc1);
    }
    float bv = bias1[c];
    if (rg < nIds) {
        int pv = g_posS[ids[rg]];
        float x = acc0 + g_h1p[(size_t)pv * FD + c] + bv;
        out[(size_t)rg * FD + c] = tanhf(eluf(x));
    }
    int r2 = rg + 8;
    if (r2 < nIds) {
        int pv = g_posS[ids[r2]];
        float x = acc1 + g_h1p[(size_t)pv * FD + c] + bv;
        out[(size_t)r2 * FD + c] = tanhf(eluf(x));
    }
}

// ---------------- launch ----------------
extern "C" void kernel_launch(void* const* d_in, const int* in_sizes, int n_in,
                              void* d_out, int out_size) {
    const float* features = (const float*)d_in[0];
    const float* fc_w0    = (const float*)d_in[1];
    const float* attn_l0  = (const float*)d_in[2];
    const float* attn_r0  = (const float*)d_in[3];
    const float* bias0    = (const float*)d_in[4];
    const float* fc_w1    = (const float*)d_in[5];
    const float* attn_l1  = (const float*)d_in[6];
    const float* attn_r1  = (const float*)d_in[7];
    const float* bias1    = (const float*)d_in[8];
    const int*   src      = (const int*)d_in[9];
    const int*   dst      = (const int*)d_in[10];
    const int*   ids      = (const int*)d_in[11];
    int E    = in_sizes[9];
    int nIds = in_sizes[11];
    float* out = (float*)d_out;

    k_setup<<<128, 256>>>(fc_w0, attn_l0, attn_r0, fc_w1, attn_l1, attn_r1);
    k_scan_e2<<<1184, 256>>>(src, dst, ids, nIds, E);
    k_scan_e1<<<1184, 256>>>(src, dst, E);

    // layer 1
    k_eler0<<<592, 256>>>(features);
    k_agg1<<<296, 256>>>(features);
    k_gemm1<<<36, GT>>>(fc_w0, bias0);

    // layer 2
    k_agg2<<<2, 512>>>(ids, nIds);
    k_final<<<16, 256>>>(fc_w1, bias1, ids, nIds, out);
}